// round 13
// baseline (speedup 1.0000x reference)
#include <cuda_runtime.h>
#include <cuda_fp16.h>
#include <cstdint>

#define D 128
#define N_TGT 40000
#define N_SRC 40000
#define N_EDGE 640000
#define TILE64 64
#define NT64 (N_EDGE / TILE64)          // 10000 edge tiles
#define NTN64 (N_TGT / TILE64)          // 625 node tiles
#define NPRE (N_SRC + N_TGT)            // 80000 precompute rows
#define NTP64 (NPRE / TILE64)           // 1250 precompute tiles
#define SROW 68                          // u32 per fp16 smem row (64 data + 4 pad)
#define XBLK (TILE64 * SROW)             // 4352 u32 per X buffer

// ---------------- scratch ----------------
__device__ float g_sums[(size_t)N_TGT * D];
__device__ float g_counts[N_TGT];
__device__ float g_ST[(size_t)NPRE * D];   // S1 rows [0,40000), T1 rows [40000,80000)

__global__ void zero_scratch_kernel() {
    const int n = N_TGT * D;
    const int total = n + N_TGT;
    for (int i = blockIdx.x * blockDim.x + threadIdx.x; i < total;
         i += gridDim.x * blockDim.x) {
        if (i < n) g_sums[i] = 0.f;
        else       g_counts[i - n] = 0.f;
    }
}

// ---------------- helpers ----------------
__device__ __forceinline__ uint32_t smem_addr_u32(const void* p) {
    uint32_t a;
    asm("{ .reg .u64 t; cvta.to.shared.u64 t, %1; cvt.u32.u64 %0, t; }"
        : "=r"(a) : "l"(p));
    return a;
}
__device__ __forceinline__ uint32_t ph2(float x, float y) {
    __half2 h = __floats2half2_rn(x, y);
    return *(uint32_t*)&h;
}
__device__ __forceinline__ void ldsm_x4(uint32_t& r0, uint32_t& r1,
                                        uint32_t& r2, uint32_t& r3, uint32_t a) {
    asm volatile("ldmatrix.sync.aligned.m8n8.x4.shared.b16 {%0,%1,%2,%3}, [%4];"
        : "=r"(r0), "=r"(r1), "=r"(r2), "=r"(r3) : "r"(a));
}
__device__ __forceinline__ void ldsm_x2(uint32_t& r0, uint32_t& r1, uint32_t a) {
    asm volatile("ldmatrix.sync.aligned.m8n8.x2.shared.b16 {%0,%1}, [%2];"
        : "=r"(r0), "=r"(r1) : "r"(a));
}
__device__ __forceinline__ void mma16(float* d, uint32_t a0, uint32_t a1,
                                      uint32_t a2, uint32_t a3,
                                      uint32_t b0, uint32_t b1) {
    asm volatile(
        "mma.sync.aligned.m16n8k16.row.col.f32.f16.f16.f32 "
        "{%0,%1,%2,%3},{%4,%5,%6,%7},{%8,%9},{%0,%1,%2,%3};"
        : "+f"(d[0]), "+f"(d[1]), "+f"(d[2]), "+f"(d[3])
        : "r"(a0), "r"(a1), "r"(a2), "r"(a3), "r"(b0), "r"(b1));
}
__device__ __forceinline__ void red_v4(float* p, float a, float b,
                                       float c, float d) {
    asm volatile("red.relaxed.gpu.global.add.v4.f32 [%0], {%1, %2, %3, %4};"
        :: "l"(p), "f"(a), "f"(b), "f"(c), "f"(d) : "memory");
}
__device__ __forceinline__ void barg(int gid) {
    asm volatile("bar.sync %0, 128;" :: "r"(gid + 1) : "memory");
}

// ---------------- smem layout (u32 offsets) ----------------
#define UOFF_W1  0
#define UOFF_W2  8704
#define UOFF_X   17408          // group g: XA = UOFF_X + g*2*XBLK, XB = XA + XBLK
#define UOFF_SUM 52224          // + g*128 floats
#define UOFF_SQ  52736          // + g*128 floats
#define UOFF_G   53248
#define UOFF_B   53376
#define SMEM_U32 53504
#define SMEM_BYTES (SMEM_U32 * 4)   // 214016

// ======================= PRE kernel: g_ST = [src;tgt] @ W1^T ================
__global__ void __launch_bounds__(512, 1)
pre_kernel(const float* __restrict__ src_feat,
           const float* __restrict__ tgt_feat,
           const float* __restrict__ W1)
{
    extern __shared__ uint32_t smu[];
    const uint32_t smb = smem_addr_u32(smu);

    const int tid  = threadIdx.x;
    const int gid  = tid >> 7;
    const int lt   = tid & 127;
    const int wid  = lt >> 5;
    const int lane = tid & 31;
    const int g    = lane >> 2;
    const int t4   = lane & 3;
    const int wr   = wid & 1;
    const int wcol = wid >> 1;
    const uint32_t xa_off = UOFF_X + gid * 2 * XBLK;

    const int a_r  = (lane & 7) + ((lane >> 3) & 1) * 8;
    const int a_cu = ((lane >> 4) & 1) * 4;
    const int lb   = lane & 15;
    const int b_r  = lb & 7;
    const int b_cu = ((lb >> 3) & 1) * 4;

    for (int i = tid; i < 128 * 32; i += 512) {
        int n = i >> 5, k4 = (i & 31) << 2;
        float4 a = *(const float4*)(W1 + n * D + k4);
        uint2 ua;
        ua.x = ph2(a.x, a.y); ua.y = ph2(a.z, a.w);
        *(uint2*)(smu + UOFF_W1 + n * SROW + (k4 >> 1)) = ua;
    }
    __syncthreads();

    for (int tile = blockIdx.x * 4 + gid; tile < NTP64; tile += gridDim.x * 4) {
        const int r0 = tile * TILE64;

#pragma unroll
        for (int j = 0; j < 16; j++) {
            int i = lt + 128 * j;
            int row = i >> 5, k4 = (i & 31) << 2;
            int r = r0 + row;
            const float* p = (r < N_SRC) ? (src_feat + (size_t)r * D + k4)
                                         : (tgt_feat + (size_t)(r - N_SRC) * D + k4);
            float4 v = *(const float4*)p;
            uint2 u;
            u.x = ph2(v.x, v.y); u.y = ph2(v.z, v.w);
            *(uint2*)(smu + xa_off + row * SROW + (k4 >> 1)) = u;
        }
        barg(gid);

        float acc[2][8][4];
#pragma unroll
        for (int mt = 0; mt < 2; mt++)
#pragma unroll
            for (int nt = 0; nt < 8; nt++)
#pragma unroll
                for (int j = 0; j < 4; j++) acc[mt][nt][j] = 0.f;

#pragma unroll
        for (int ks = 0; ks < 8; ks++) {
            uint32_t a0[2], a1[2], a2[2], a3[2];
#pragma unroll
            for (int mt = 0; mt < 2; mt++) {
                uint32_t ad = smb + (xa_off + (wr * 32 + mt * 16 + a_r) * SROW
                                     + ks * 8 + a_cu) * 4;
                ldsm_x4(a0[mt], a1[mt], a2[mt], a3[mt], ad);
            }
#pragma unroll
            for (int nt = 0; nt < 8; nt++) {
                uint32_t bd = smb + (UOFF_W1 + (wcol * 64 + nt * 8 + b_r) * SROW
                                     + ks * 8 + b_cu) * 4;
                uint32_t b0, b1;
                ldsm_x2(b0, b1, bd);
                mma16(acc[0][nt], a0[0], a1[0], a2[0], a3[0], b0, b1);
                mma16(acc[1][nt], a0[1], a1[1], a2[1], a3[1], b0, b1);
            }
        }
        barg(gid);   // all ldsm of XA done before next staging

#pragma unroll
        for (int mt = 0; mt < 2; mt++) {
#pragma unroll
            for (int h = 0; h < 2; h++) {
                const int row = wr * 32 + mt * 16 + h * 8 + g;
                float* __restrict__ orow = g_ST + (size_t)(r0 + row) * D;
#pragma unroll
                for (int nt = 0; nt < 8; nt++) {
                    const int c = wcol * 64 + nt * 8 + t4 * 2;
                    float a0 = acc[mt][nt][h * 2 + 0];
                    float a1 = acc[mt][nt][h * 2 + 1];
                    float p0 = __shfl_xor_sync(0xffffffffu, a0, 1);
                    float p1 = __shfl_xor_sync(0xffffffffu, a1, 1);
                    if ((t4 & 1) == 0)
                        *(float4*)(orow + c) = make_float4(a0, a1, p0, p1);
                }
            }
        }
    }
}

// ======================= EDGE kernel (1 MMA pass + gathered pass-1) ========
__global__ void __launch_bounds__(512, 1)
edge_kernel(const float* __restrict__ edge_feat,
            const float* __restrict__ W2,
            const float* __restrict__ gamma,
            const float* __restrict__ beta,
            const int*   __restrict__ src_idx,
            const int*   __restrict__ tgt_idx,
            float*       __restrict__ out)
{
    extern __shared__ uint32_t smu[];
    const uint32_t smb = smem_addr_u32(smu);

    float* s_sum = nullptr; float* s_sq = nullptr;
    const int tid  = threadIdx.x;
    const int gid  = tid >> 7;
    const int lt   = tid & 127;
    const int wid  = lt >> 5;
    const int lane = tid & 31;
    const int g    = lane >> 2;
    const int t4   = lane & 3;
    const int wr   = wid & 1;
    const int wcol = wid >> 1;

    s_sum = (float*)(smu + UOFF_SUM + gid * 128);
    s_sq  = (float*)(smu + UOFF_SQ  + gid * 128);
    float* s_g = (float*)(smu + UOFF_G);
    float* s_b = (float*)(smu + UOFF_B);
    const uint32_t xa_off = UOFF_X + gid * 2 * XBLK;   // fp16 pass-1 sum (LDS)
    const uint32_t xb_off = xa_off + XBLK;             // fp16 edge rows (ldmatrix)

    const int a_r  = (lane & 7) + ((lane >> 3) & 1) * 8;
    const int a_cu = ((lane >> 4) & 1) * 4;
    const int lb   = lane & 15;
    const int b_r  = lb & 7;
    const int b_cu = ((lb >> 3) & 1) * 4;

    if (tid < 128) { s_g[tid] = gamma[tid]; s_b[tid] = beta[tid]; }

    // stage W2 (fp16)
    for (int i = tid; i < 128 * 32; i += 512) {
        int n = i >> 5, k4 = (i & 31) << 2;
        float4 b = *(const float4*)(W2 + n * D + k4);
        uint2 ub;
        ub.x = ph2(b.x, b.y); ub.y = ph2(b.z, b.w);
        *(uint2*)(smu + UOFF_W2 + n * SROW + (k4 >> 1)) = ub;
    }
    __syncthreads();

    for (int tile = blockIdx.x * 4 + gid; tile < NT64; tile += gridDim.x * 4) {
        const int m0 = tile * TILE64;

        // ---- stage XA = S1[si]+T1[ti] (fp16), XB = edge (fp16) ----
#pragma unroll
        for (int j = 0; j < 16; j++) {
            int i = lt + 128 * j;
            int row = i >> 5, k4 = (i & 31) << 2;
            int si = src_idx[m0 + row];
            int ti = tgt_idx[m0 + row];
            float4 a = *(const float4*)(g_ST + (size_t)si * D + k4);
            float4 b = *(const float4*)(g_ST + (size_t)(N_SRC + ti) * D + k4);
            float4 e = *(const float4*)(edge_feat + (size_t)(m0 + row) * D + k4);
            uint2 u0, u1;
            u0.x = ph2(a.x + b.x, a.y + b.y);
            u0.y = ph2(a.z + b.z, a.w + b.w);
            u1.x = ph2(e.x, e.y);
            u1.y = ph2(e.z, e.w);
            *(uint2*)(smu + xa_off + row * SROW + (k4 >> 1)) = u0;
            *(uint2*)(smu + xb_off + row * SROW + (k4 >> 1)) = u1;
        }
        barg(gid);

        float acc[2][8][4];
#pragma unroll
        for (int mt = 0; mt < 2; mt++)
#pragma unroll
            for (int nt = 0; nt < 8; nt++)
#pragma unroll
                for (int j = 0; j < 4; j++) acc[mt][nt][j] = 0.f;

        // ---- single MMA pass: acc = XB @ W2^T ----
#pragma unroll
        for (int ks = 0; ks < 8; ks++) {
            uint32_t a0[2], a1[2], a2[2], a3[2];
#pragma unroll
            for (int mt = 0; mt < 2; mt++) {
                uint32_t ad = smb + (xb_off + (wr * 32 + mt * 16 + a_r) * SROW
                                     + ks * 8 + a_cu) * 4;
                ldsm_x4(a0[mt], a1[mt], a2[mt], a3[mt], ad);
            }
#pragma unroll
            for (int nt = 0; nt < 8; nt++) {
                uint32_t bd = smb + (UOFF_W2 + (wcol * 64 + nt * 8 + b_r) * SROW
                                     + ks * 8 + b_cu) * 4;
                uint32_t b0, b1;
                ldsm_x2(b0, b1, bd);
                mma16(acc[0][nt], a0[0], a1[0], a2[0], a3[0], b0, b1);
                mma16(acc[1][nt], a0[1], a1[1], a2[1], a3[1], b0, b1);
            }
        }

        // ---- add gathered pass-1 (XA), then silu + LN partials ----
#pragma unroll
        for (int mt = 0; mt < 2; mt++) {
#pragma unroll
            for (int h = 0; h < 2; h++) {
                const int row = wr * 32 + mt * 16 + h * 8 + g;
                float s = 0.f, q = 0.f;
#pragma unroll
                for (int nt = 0; nt < 8; nt++) {
                    const int c = wcol * 64 + nt * 8 + t4 * 2;
                    uint32_t u = smu[xa_off + row * SROW + (c >> 1)];
                    __half2 hv = *reinterpret_cast<__half2*>(&u);
                    float2 f = __half22float2(hv);
#pragma unroll
                    for (int j = 0; j < 2; j++) {
                        float v  = acc[mt][nt][h * 2 + j] + (j ? f.y : f.x);
                        float sv = v / (1.f + __expf(-v));
                        acc[mt][nt][h * 2 + j] = sv;
                        s += sv; q += sv * sv;
                    }
                }
                s += __shfl_xor_sync(0xffffffffu, s, 1);
                s += __shfl_xor_sync(0xffffffffu, s, 2);
                q += __shfl_xor_sync(0xffffffffu, q, 1);
                q += __shfl_xor_sync(0xffffffffu, q, 2);
                if (t4 == 0) {
                    s_sum[wcol * 64 + row] = s;
                    s_sq[wcol * 64 + row]  = q;
                }
            }
        }
        barg(gid);

        // ---- LN + residual + out + scatter ----
#pragma unroll
        for (int mt = 0; mt < 2; mt++) {
#pragma unroll
            for (int h = 0; h < 2; h++) {
                const int row = wr * 32 + mt * 16 + h * 8 + g;
                const float tsum = s_sum[row] + s_sum[64 + row];
                const float tsq  = s_sq[row]  + s_sq[64 + row];
                const float mean = tsum * (1.f / 128.f);
                const float inv  = rsqrtf(tsq * (1.f / 128.f) - mean * mean + 1e-5f);
                const int    t   = tgt_idx[m0 + row];
                const size_t gm  = (size_t)(m0 + row);
                float* __restrict__ srow = g_sums + (size_t)t * D;
                const float* __restrict__ er = edge_feat + gm * D;
                float* __restrict__ orow = out + gm * D;
#pragma unroll
                for (int nt = 0; nt < 8; nt++) {
                    const int c = wcol * 64 + nt * 8 + t4 * 2;
                    float a0 = (acc[mt][nt][h * 2 + 0] - mean) * inv * s_g[c + 0] + s_b[c + 0];
                    float a1 = (acc[mt][nt][h * 2 + 1] - mean) * inv * s_g[c + 1] + s_b[c + 1];
                    float p0 = __shfl_xor_sync(0xffffffffu, a0, 1);
                    float p1 = __shfl_xor_sync(0xffffffffu, a1, 1);
                    if ((t4 & 1) == 0) {
                        float4 rs = *(const float4*)(er + c);
                        float4 o;
                        o.x = rs.x + a0; o.y = rs.y + a1;
                        o.z = rs.z + p0; o.w = rs.w + p1;
                        *(float4*)(orow + c) = o;
                        red_v4(srow + c, a0, a1, p0, p1);
                    }
                }
                if (wcol == 0 && t4 == 0) atomicAdd(g_counts + t, 1.f);
            }
        }
        // no trailing barrier: XA reads all precede the LN barrier; s_sum
        // reuse is ordered by the next stage barrier.
    }
}

// ======================= NODE kernel (two MMA passes, as R12) ==============
__global__ void __launch_bounds__(512, 1)
node_kernel(const float* __restrict__ tgt_feat,
            const float* __restrict__ W1,       // We2t
            const float* __restrict__ W2,       // Wt2t
            const float* __restrict__ gamma,
            const float* __restrict__ beta,
            float*       __restrict__ out)
{
    extern __shared__ uint32_t smu[];
    const uint32_t smb = smem_addr_u32(smu);

    const int tid  = threadIdx.x;
    const int gid  = tid >> 7;
    const int lt   = tid & 127;
    const int wid  = lt >> 5;
    const int lane = tid & 31;
    const int g    = lane >> 2;
    const int t4   = lane & 3;
    const int wr   = wid & 1;
    const int wcol = wid >> 1;

    float* s_sum = (float*)(smu + UOFF_SUM + gid * 128);
    float* s_sq  = (float*)(smu + UOFF_SQ  + gid * 128);
    float* s_g   = (float*)(smu + UOFF_G);
    float* s_b   = (float*)(smu + UOFF_B);
    const uint32_t xa_off = UOFF_X + gid * 2 * XBLK;
    const uint32_t xb_off = xa_off + XBLK;

    const int a_r  = (lane & 7) + ((lane >> 3) & 1) * 8;
    const int a_cu = ((lane >> 4) & 1) * 4;
    const int lb   = lane & 15;
    const int b_r  = lb & 7;
    const int b_cu = ((lb >> 3) & 1) * 4;

    if (tid < 128) { s_g[tid] = gamma[tid]; s_b[tid] = beta[tid]; }

    for (int i = tid; i < 128 * 32; i += 512) {
        int n = i >> 5, k4 = (i & 31) << 2;
        float4 a = *(const float4*)(W1 + n * D + k4);
        float4 b = *(const float4*)(W2 + n * D + k4);
        uint2 ua, ub;
        ua.x = ph2(a.x, a.y); ua.y = ph2(a.z, a.w);
        ub.x = ph2(b.x, b.y); ub.y = ph2(b.z, b.w);
        *(uint2*)(smu + UOFF_W1 + n * SROW + (k4 >> 1)) = ua;
        *(uint2*)(smu + UOFF_W2 + n * SROW + (k4 >> 1)) = ub;
    }
    __syncthreads();

    for (int tile = blockIdx.x * 4 + gid; tile < NTN64; tile += gridDim.x * 4) {
        const int m0 = tile * TILE64;

#pragma unroll
        for (int j = 0; j < 16; j++) {
            int i = lt + 128 * j;
            int row = i >> 5, k4 = (i & 31) << 2;
            size_t gm = (size_t)(m0 + row);
            float inv = 1.f / fmaxf(g_counts[gm], 1.f);
            float4 a = *(const float4*)(g_sums + gm * D + k4);
            float4 e = *(const float4*)(tgt_feat + gm * D + k4);
            uint2 u0, u1;
            u0.x = ph2(a.x * inv, a.y * inv);
            u0.y = ph2(a.z * inv, a.w * inv);
            u1.x = ph2(e.x, e.y);
            u1.y = ph2(e.z, e.w);
            *(uint2*)(smu + xa_off + row * SROW + (k4 >> 1)) = u0;
            *(uint2*)(smu + xb_off + row * SROW + (k4 >> 1)) = u1;
        }
        barg(gid);

        float acc[2][8][4];
#pragma unroll
        for (int mt = 0; mt < 2; mt++)
#pragma unroll
            for (int nt = 0; nt < 8; nt++)
#pragma unroll
                for (int j = 0; j < 4; j++) acc[mt][nt][j] = 0.f;

#pragma unroll
        for (int ks = 0; ks < 8; ks++) {
            uint32_t a0[2], a1[2], a2[2], a3[2];
#pragma unroll
            for (int mt = 0; mt < 2; mt++) {
                uint32_t ad = smb + (xa_off + (wr * 32 + mt * 16 + a_r) * SROW
                                     + ks * 8 + a_cu) * 4;
                ldsm_x4(a0[mt], a1[mt], a2[mt], a3[mt], ad);
            }
#pragma unroll
            for (int nt = 0; nt < 8; nt++) {
                uint32_t bd = smb + (UOFF_W1 + (wcol * 64 + nt * 8 + b_r) * SROW
                                     + ks * 8 + b_cu) * 4;
                uint32_t b0, b1;
                ldsm_x2(b0, b1, bd);
                mma16(acc[0][nt], a0[0], a1[0], a2[0], a3[0], b0, b1);
                mma16(acc[1][nt], a0[1], a1[1], a2[1], a3[1], b0, b1);
            }
        }
#pragma unroll
        for (int ks = 0; ks < 8; ks++) {
            uint32_t a0[2], a1[2], a2[2], a3[2];
#pragma unroll
            for (int mt = 0; mt < 2; mt++) {
                uint32_t ad = smb + (xb_off + (wr * 32 + mt * 16 + a_r) * SROW
                                     + ks * 8 + a_cu) * 4;
                ldsm_x4(a0[mt], a1[mt], a2[mt], a3[mt], ad);
            }
#pragma unroll
            for (int nt = 0; nt < 8; nt++) {
                uint32_t bd = smb + (UOFF_W2 + (wcol * 64 + nt * 8 + b_r) * SROW
                                     + ks * 8 + b_cu) * 4;
                uint32_t b0, b1;
                ldsm_x2(b0, b1, bd);
                mma16(acc[0][nt], a0[0], a1[0], a2[0], a3[0], b0, b1);
                mma16(acc[1][nt], a0[1], a1[1], a2[1], a3[1], b0, b1);
            }
        }

#pragma unroll
        for (int mt = 0; mt < 2; mt++) {
#pragma unroll
            for (int h = 0; h < 2; h++) {
                float s = 0.f, q = 0.f;
#pragma unroll
                for (int nt = 0; nt < 8; nt++) {
#pragma unroll
                    for (int j = 0; j < 2; j++) {
                        float v  = acc[mt][nt][h * 2 + j];
                        float sv = v / (1.f + __expf(-v));
                        acc[mt][nt][h * 2 + j] = sv;
                        s += sv; q += sv * sv;
                    }
                }
                s += __shfl_xor_sync(0xffffffffu, s, 1);
                s += __shfl_xor_sync(0xffffffffu, s, 2);
                q += __shfl_xor_sync(0xffffffffu, q, 1);
                q += __shfl_xor_sync(0xffffffffu, q, 2);
                if (t4 == 0) {
                    int row = wr * 32 + mt * 16 + h * 8 + g;
                    s_sum[wcol * 64 + row] = s;
                    s_sq[wcol * 64 + row]  = q;
                }
            }
        }
        barg(gid);

#pragma unroll
        for (int mt = 0; mt < 2; mt++) {
#pragma unroll
            for (int h = 0; h < 2; h++) {
                const int row = wr * 32 + mt * 16 + h * 8 + g;
                const float tsum = s_sum[row] + s_sum[64 + row];
                const float tsq  = s_sq[row]  + s_sq[64 + row];
                const float mean = tsum * (1.f / 128.f);
                const float inv  = rsqrtf(tsq * (1.f / 128.f) - mean * mean + 1e-5f);
                const size_t gm  = (size_t)(m0 + row);
                const float* __restrict__ er = tgt_feat + gm * D;
                float* __restrict__ orow = out + gm * D;
#pragma unroll
                for (int nt = 0; nt < 8; nt++) {
                    const int c = wcol * 64 + nt * 8 + t4 * 2;
                    float a0 = (acc[mt][nt][h * 2 + 0] - mean) * inv * s_g[c + 0] + s_b[c + 0];
                    float a1 = (acc[mt][nt][h * 2 + 1] - mean) * inv * s_g[c + 1] + s_b[c + 1];
                    float p0 = __shfl_xor_sync(0xffffffffu, a0, 1);
                    float p1 = __shfl_xor_sync(0xffffffffu, a1, 1);
                    if ((t4 & 1) == 0) {
                        float4 rs = *(const float4*)(er + c);
                        *(float4*)(orow + c) = make_float4(rs.x + a0, rs.y + a1,
                                                           rs.z + p0, rs.w + p1);
                    }
                }
            }
        }
    }
}

// ======================= launch =======================
extern "C" void kernel_launch(void* const* d_in, const int* in_sizes, int n_in,
                              void* d_out, int out_size) {
    const float* src_feat  = (const float*)d_in[0];
    const float* tgt_feat  = (const float*)d_in[1];
    const float* edge_feat = (const float*)d_in[2];
    const float* Ws2e      = (const float*)d_in[3];
    const float* We2e      = (const float*)d_in[4];
    const float* We2t      = (const float*)d_in[5];
    const float* Wt2t      = (const float*)d_in[6];
    const float* gamma1    = (const float*)d_in[7];
    const float* beta1     = (const float*)d_in[8];
    const float* gamma2    = (const float*)d_in[9];
    const float* beta2     = (const float*)d_in[10];
    const int*   src_idx   = (const int*)d_in[11];
    const int*   tgt_idx   = (const int*)d_in[12];
    float*       out       = (float*)d_out;

    cudaFuncSetAttribute(pre_kernel,
                         cudaFuncAttributeMaxDynamicSharedMemorySize, SMEM_BYTES);
    cudaFuncSetAttribute(edge_kernel,
                         cudaFuncAttributeMaxDynamicSharedMemorySize, SMEM_BYTES);
    cudaFuncSetAttribute(node_kernel,
                         cudaFuncAttributeMaxDynamicSharedMemorySize, SMEM_BYTES);

    zero_scratch_kernel<<<2048, 256>>>();

    pre_kernel<<<148, 512, SMEM_BYTES>>>(src_feat, tgt_feat, Ws2e);

    edge_kernel<<<148, 512, SMEM_BYTES>>>(
        edge_feat, We2e, gamma1, beta1, src_idx, tgt_idx, out);

    node_kernel<<<148, 512, SMEM_BYTES>>>(
        tgt_feat, We2t, Wt2t, gamma2, beta2, out + (size_t)N_EDGE * D);
}

// round 15
// speedup vs baseline: 1.0752x; 1.0752x over previous
#include <cuda_runtime.h>
#include <cuda_fp16.h>
#include <cstdint>

#define D 128
#define N_TGT 40000
#define N_SRC 40000
#define N_EDGE 640000
#define TILE64 64
#define NT64 (N_EDGE / TILE64)          // 10000 edge tiles
#define NTN64 (N_TGT / TILE64)          // 625 node tiles
#define NPRE (N_SRC + N_TGT)            // 80000 precompute rows
#define NTP64 (NPRE / TILE64)           // 1250 precompute tiles
#define SROW 68                          // u32 per fp16 smem row (64 data + 4 pad)
#define XBLK (TILE64 * SROW)             // 4352 u32 per X buffer

// ---------------- scratch ----------------
__device__ float g_sums[(size_t)N_TGT * D];
__device__ float g_counts[N_TGT];
__device__ float g_ST[(size_t)NPRE * D];   // S1 rows [0,40000), T1 rows [40000,80000)

__global__ void zero_scratch_kernel() {
    const int n = N_TGT * D;
    const int total = n + N_TGT;
    for (int i = blockIdx.x * blockDim.x + threadIdx.x; i < total;
         i += gridDim.x * blockDim.x) {
        if (i < n) g_sums[i] = 0.f;
        else       g_counts[i - n] = 0.f;
    }
}

// ---------------- helpers ----------------
__device__ __forceinline__ uint32_t smem_addr_u32(const void* p) {
    uint32_t a;
    asm("{ .reg .u64 t; cvta.to.shared.u64 t, %1; cvt.u32.u64 %0, t; }"
        : "=r"(a) : "l"(p));
    return a;
}
__device__ __forceinline__ uint32_t ph2(float x, float y) {
    __half2 h = __floats2half2_rn(x, y);
    return *(uint32_t*)&h;
}
__device__ __forceinline__ void ldsm_x4(uint32_t& r0, uint32_t& r1,
                                        uint32_t& r2, uint32_t& r3, uint32_t a) {
    asm volatile("ldmatrix.sync.aligned.m8n8.x4.shared.b16 {%0,%1,%2,%3}, [%4];"
        : "=r"(r0), "=r"(r1), "=r"(r2), "=r"(r3) : "r"(a));
}
__device__ __forceinline__ void ldsm_x2(uint32_t& r0, uint32_t& r1, uint32_t a) {
    asm volatile("ldmatrix.sync.aligned.m8n8.x2.shared.b16 {%0,%1}, [%2];"
        : "=r"(r0), "=r"(r1) : "r"(a));
}
__device__ __forceinline__ void mma16(float* d, uint32_t a0, uint32_t a1,
                                      uint32_t a2, uint32_t a3,
                                      uint32_t b0, uint32_t b1) {
    asm volatile(
        "mma.sync.aligned.m16n8k16.row.col.f32.f16.f16.f32 "
        "{%0,%1,%2,%3},{%4,%5,%6,%7},{%8,%9},{%0,%1,%2,%3};"
        : "+f"(d[0]), "+f"(d[1]), "+f"(d[2]), "+f"(d[3])
        : "r"(a0), "r"(a1), "r"(a2), "r"(a3), "r"(b0), "r"(b1));
}
__device__ __forceinline__ void red_v4(float* p, float a, float b,
                                       float c, float d) {
    asm volatile("red.relaxed.gpu.global.add.v4.f32 [%0], {%1, %2, %3, %4};"
        :: "l"(p), "f"(a), "f"(b), "f"(c), "f"(d) : "memory");
}
__device__ __forceinline__ void barg(int gid) {
    asm volatile("bar.sync %0, 128;" :: "r"(gid + 1) : "memory");
}

// ---------------- smem layout (u32 offsets) ----------------
#define UOFF_W1  0
#define UOFF_W2  8704
#define UOFF_X   17408          // group g: XA = UOFF_X + g*2*XBLK, XB = XA + XBLK
#define UOFF_SUM 52224          // + g*128 floats
#define UOFF_SQ  52736          // + g*128 floats
#define UOFF_G   53248
#define UOFF_B   53376
#define SMEM_U32 53504
#define SMEM_BYTES (SMEM_U32 * 4)   // 214016

// ======================= PRE kernel: g_ST = [src;tgt] @ W1^T ================
__global__ void __launch_bounds__(512, 1)
pre_kernel(const float* __restrict__ src_feat,
           const float* __restrict__ tgt_feat,
           const float* __restrict__ W1)
{
    extern __shared__ uint32_t smu[];
    const uint32_t smb = smem_addr_u32(smu);

    const int tid  = threadIdx.x;
    const int gid  = tid >> 7;
    const int lt   = tid & 127;
    const int wid  = lt >> 5;
    const int lane = tid & 31;
    const int g    = lane >> 2;
    const int t4   = lane & 3;
    const int wr   = wid & 1;
    const int wcol = wid >> 1;
    const uint32_t xa_off = UOFF_X + gid * 2 * XBLK;

    const int a_r  = (lane & 7) + ((lane >> 3) & 1) * 8;
    const int a_cu = ((lane >> 4) & 1) * 4;
    const int lb   = lane & 15;
    const int b_r  = lb & 7;
    const int b_cu = ((lb >> 3) & 1) * 4;

    for (int i = tid; i < 128 * 32; i += 512) {
        int n = i >> 5, k4 = (i & 31) << 2;
        float4 a = *(const float4*)(W1 + n * D + k4);
        uint2 ua;
        ua.x = ph2(a.x, a.y); ua.y = ph2(a.z, a.w);
        *(uint2*)(smu + UOFF_W1 + n * SROW + (k4 >> 1)) = ua;
    }
    __syncthreads();

    for (int tile = blockIdx.x * 4 + gid; tile < NTP64; tile += gridDim.x * 4) {
        const int r0 = tile * TILE64;

#pragma unroll
        for (int j = 0; j < 16; j++) {
            int i = lt + 128 * j;
            int row = i >> 5, k4 = (i & 31) << 2;
            int r = r0 + row;
            const float* p = (r < N_SRC) ? (src_feat + (size_t)r * D + k4)
                                         : (tgt_feat + (size_t)(r - N_SRC) * D + k4);
            float4 v = *(const float4*)p;
            uint2 u;
            u.x = ph2(v.x, v.y); u.y = ph2(v.z, v.w);
            *(uint2*)(smu + xa_off + row * SROW + (k4 >> 1)) = u;
        }
        barg(gid);

        float acc[2][8][4];
#pragma unroll
        for (int mt = 0; mt < 2; mt++)
#pragma unroll
            for (int nt = 0; nt < 8; nt++)
#pragma unroll
                for (int j = 0; j < 4; j++) acc[mt][nt][j] = 0.f;

#pragma unroll
        for (int ks = 0; ks < 8; ks++) {
            uint32_t a0[2], a1[2], a2[2], a3[2];
#pragma unroll
            for (int mt = 0; mt < 2; mt++) {
                uint32_t ad = smb + (xa_off + (wr * 32 + mt * 16 + a_r) * SROW
                                     + ks * 8 + a_cu) * 4;
                ldsm_x4(a0[mt], a1[mt], a2[mt], a3[mt], ad);
            }
#pragma unroll
            for (int nt = 0; nt < 8; nt++) {
                uint32_t bd = smb + (UOFF_W1 + (wcol * 64 + nt * 8 + b_r) * SROW
                                     + ks * 8 + b_cu) * 4;
                uint32_t b0, b1;
                ldsm_x2(b0, b1, bd);
                mma16(acc[0][nt], a0[0], a1[0], a2[0], a3[0], b0, b1);
                mma16(acc[1][nt], a0[1], a1[1], a2[1], a3[1], b0, b1);
            }
        }
        barg(gid);   // all ldsm of XA done before next staging

#pragma unroll
        for (int mt = 0; mt < 2; mt++) {
#pragma unroll
            for (int h = 0; h < 2; h++) {
                const int row = wr * 32 + mt * 16 + h * 8 + g;
                float* __restrict__ orow = g_ST + (size_t)(r0 + row) * D;
#pragma unroll
                for (int nt = 0; nt < 8; nt++) {
                    const int c = wcol * 64 + nt * 8 + t4 * 2;
                    float a0 = acc[mt][nt][h * 2 + 0];
                    float a1 = acc[mt][nt][h * 2 + 1];
                    float p0 = __shfl_xor_sync(0xffffffffu, a0, 1);
                    float p1 = __shfl_xor_sync(0xffffffffu, a1, 1);
                    if ((t4 & 1) == 0)
                        *(float4*)(orow + c) = make_float4(a0, a1, p0, p1);
                }
            }
        }
    }
}

// ======================= EDGE kernel (1 MMA pass + gathered pass-1) ========
__global__ void __launch_bounds__(512, 1)
edge_kernel(const float* __restrict__ edge_feat,
            const float* __restrict__ W2,
            const float* __restrict__ gamma,
            const float* __restrict__ beta,
            const int*   __restrict__ src_idx,
            const int*   __restrict__ tgt_idx,
            float*       __restrict__ out)
{
    extern __shared__ uint32_t smu[];
    const uint32_t smb = smem_addr_u32(smu);

    const int tid  = threadIdx.x;
    const int gid  = tid >> 7;
    const int lt   = tid & 127;
    const int wid  = lt >> 5;
    const int lane = tid & 31;
    const int g    = lane >> 2;
    const int t4   = lane & 3;
    const int wr   = wid & 1;
    const int wcol = wid >> 1;

    float* s_sum = (float*)(smu + UOFF_SUM + gid * 128);
    float* s_sq  = (float*)(smu + UOFF_SQ  + gid * 128);
    float* s_g = (float*)(smu + UOFF_G);
    float* s_b = (float*)(smu + UOFF_B);
    const uint32_t xa_off = UOFF_X + gid * 2 * XBLK;   // fp16 pass-1 sum (LDS)
    const uint32_t xb_off = xa_off + XBLK;             // fp16 edge rows

    const int a_r  = (lane & 7) + ((lane >> 3) & 1) * 8;
    const int a_cu = ((lane >> 4) & 1) * 4;
    const int lb   = lane & 15;
    const int b_r  = lb & 7;
    const int b_cu = ((lb >> 3) & 1) * 4;

    if (tid < 128) { s_g[tid] = gamma[tid]; s_b[tid] = beta[tid]; }

    // stage W2 (fp16)
    for (int i = tid; i < 128 * 32; i += 512) {
        int n = i >> 5, k4 = (i & 31) << 2;
        float4 b = *(const float4*)(W2 + n * D + k4);
        uint2 ub;
        ub.x = ph2(b.x, b.y); ub.y = ph2(b.z, b.w);
        *(uint2*)(smu + UOFF_W2 + n * SROW + (k4 >> 1)) = ub;
    }
    __syncthreads();

    for (int tile = blockIdx.x * 4 + gid; tile < NT64; tile += gridDim.x * 4) {
        const int m0 = tile * TILE64;

        // ---- stage XA = S1[si]+T1[ti] (fp16), XB = edge (fp16) ----
#pragma unroll
        for (int j = 0; j < 16; j++) {
            int i = lt + 128 * j;
            int row = i >> 5, k4 = (i & 31) << 2;
            int si = src_idx[m0 + row];
            int ti = tgt_idx[m0 + row];
            float4 a = *(const float4*)(g_ST + (size_t)si * D + k4);
            float4 b = *(const float4*)(g_ST + (size_t)(N_SRC + ti) * D + k4);
            float4 e = *(const float4*)(edge_feat + (size_t)(m0 + row) * D + k4);
            uint2 u0, u1;
            u0.x = ph2(a.x + b.x, a.y + b.y);
            u0.y = ph2(a.z + b.z, a.w + b.w);
            u1.x = ph2(e.x, e.y);
            u1.y = ph2(e.z, e.w);
            *(uint2*)(smu + xa_off + row * SROW + (k4 >> 1)) = u0;
            *(uint2*)(smu + xb_off + row * SROW + (k4 >> 1)) = u1;
        }
        barg(gid);

        float acc[2][8][4];
#pragma unroll
        for (int mt = 0; mt < 2; mt++)
#pragma unroll
            for (int nt = 0; nt < 8; nt++)
#pragma unroll
                for (int j = 0; j < 4; j++) acc[mt][nt][j] = 0.f;

        // ---- single MMA pass: acc = XB @ W2^T ----
#pragma unroll
        for (int ks = 0; ks < 8; ks++) {
            uint32_t a0[2], a1[2], a2[2], a3[2];
#pragma unroll
            for (int mt = 0; mt < 2; mt++) {
                uint32_t ad = smb + (xb_off + (wr * 32 + mt * 16 + a_r) * SROW
                                     + ks * 8 + a_cu) * 4;
                ldsm_x4(a0[mt], a1[mt], a2[mt], a3[mt], ad);
            }
#pragma unroll
            for (int nt = 0; nt < 8; nt++) {
                uint32_t bd = smb + (UOFF_W2 + (wcol * 64 + nt * 8 + b_r) * SROW
                                     + ks * 8 + b_cu) * 4;
                uint32_t b0, b1;
                ldsm_x2(b0, b1, bd);
                mma16(acc[0][nt], a0[0], a1[0], a2[0], a3[0], b0, b1);
                mma16(acc[1][nt], a0[1], a1[1], a2[1], a3[1], b0, b1);
            }
        }

        // ---- add gathered pass-1 (XA), then silu + LN partials ----
#pragma unroll
        for (int mt = 0; mt < 2; mt++) {
#pragma unroll
            for (int h = 0; h < 2; h++) {
                const int row = wr * 32 + mt * 16 + h * 8 + g;
                float s = 0.f, q = 0.f;
#pragma unroll
                for (int nt = 0; nt < 8; nt++) {
                    const int c = wcol * 64 + nt * 8 + t4 * 2;
                    uint32_t u = smu[xa_off + row * SROW + (c >> 1)];
                    __half2 hv = *reinterpret_cast<__half2*>(&u);
                    float2 f = __half22float2(hv);
#pragma unroll
                    for (int j = 0; j < 2; j++) {
                        float v  = acc[mt][nt][h * 2 + j] + (j ? f.y : f.x);
                        float sv = v / (1.f + __expf(-v));
                        acc[mt][nt][h * 2 + j] = sv;
                        s += sv; q += sv * sv;
                    }
                }
                s += __shfl_xor_sync(0xffffffffu, s, 1);
                s += __shfl_xor_sync(0xffffffffu, s, 2);
                q += __shfl_xor_sync(0xffffffffu, q, 1);
                q += __shfl_xor_sync(0xffffffffu, q, 2);
                if (t4 == 0) {
                    s_sum[wcol * 64 + row] = s;
                    s_sq[wcol * 64 + row]  = q;
                }
            }
        }
        barg(gid);

        // ---- LN + residual(from fp16 XB in smem) + out + scatter ----
#pragma unroll
        for (int mt = 0; mt < 2; mt++) {
#pragma unroll
            for (int h = 0; h < 2; h++) {
                const int row = wr * 32 + mt * 16 + h * 8 + g;
                const float tsum = s_sum[row] + s_sum[64 + row];
                const float tsq  = s_sq[row]  + s_sq[64 + row];
                const float mean = tsum * (1.f / 128.f);
                const float inv  = rsqrtf(tsq * (1.f / 128.f) - mean * mean + 1e-5f);
                const int    t   = tgt_idx[m0 + row];
                const size_t gm  = (size_t)(m0 + row);
                float* __restrict__ srow = g_sums + (size_t)t * D;
                float* __restrict__ orow = out + gm * D;
#pragma unroll
                for (int nt = 0; nt < 8; nt++) {
                    const int c = wcol * 64 + nt * 8 + t4 * 2;
                    float a0 = (acc[mt][nt][h * 2 + 0] - mean) * inv * s_g[c + 0] + s_b[c + 0];
                    float a1 = (acc[mt][nt][h * 2 + 1] - mean) * inv * s_g[c + 1] + s_b[c + 1];
                    float p0 = __shfl_xor_sync(0xffffffffu, a0, 1);
                    float p1 = __shfl_xor_sync(0xffffffffu, a1, 1);
                    if ((t4 & 1) == 0) {
                        // residual from staged fp16 edge rows (4 cols = uint2)
                        uint2 ue = *(const uint2*)(smu + xb_off + row * SROW + (c >> 1));
                        float2 e0 = __half22float2(*reinterpret_cast<__half2*>(&ue.x));
                        float2 e1 = __half22float2(*reinterpret_cast<__half2*>(&ue.y));
                        *(float4*)(orow + c) = make_float4(e0.x + a0, e0.y + a1,
                                                           e1.x + p0, e1.y + p1);
                        red_v4(srow + c, a0, a1, p0, p1);
                    }
                }
                if (wcol == 0 && t4 == 0) atomicAdd(g_counts + t, 1.f);
            }
        }
        // no trailing barrier: XA/XB reads all precede the next stage barrier's
        // ordering of buffer reuse via s_sum path.
        barg(gid);
    }
}

// ======================= NODE kernel (two MMA passes, as R12) ==============
__global__ void __launch_bounds__(512, 1)
node_kernel(const float* __restrict__ tgt_feat,
            const float* __restrict__ W1,       // We2t
            const float* __restrict__ W2,       // Wt2t
            const float* __restrict__ gamma,
            const float* __restrict__ beta,
            float*       __restrict__ out)
{
    extern __shared__ uint32_t smu[];
    const uint32_t smb = smem_addr_u32(smu);

    const int tid  = threadIdx.x;
    const int gid  = tid >> 7;
    const int lt   = tid & 127;
    const int wid  = lt >> 5;
    const int lane = tid & 31;
    const int g    = lane >> 2;
    const int t4   = lane & 3;
    const int wr   = wid & 1;
    const int wcol = wid >> 1;

    float* s_sum = (float*)(smu + UOFF_SUM + gid * 128);
    float* s_sq  = (float*)(smu + UOFF_SQ  + gid * 128);
    float* s_g   = (float*)(smu + UOFF_G);
    float* s_b   = (float*)(smu + UOFF_B);
    const uint32_t xa_off = UOFF_X + gid * 2 * XBLK;
    const uint32_t xb_off = xa_off + XBLK;

    const int a_r  = (lane & 7) + ((lane >> 3) & 1) * 8;
    const int a_cu = ((lane >> 4) & 1) * 4;
    const int lb   = lane & 15;
    const int b_r  = lb & 7;
    const int b_cu = ((lb >> 3) & 1) * 4;

    if (tid < 128) { s_g[tid] = gamma[tid]; s_b[tid] = beta[tid]; }

    for (int i = tid; i < 128 * 32; i += 512) {
        int n = i >> 5, k4 = (i & 31) << 2;
        float4 a = *(const float4*)(W1 + n * D + k4);
        float4 b = *(const float4*)(W2 + n * D + k4);
        uint2 ua, ub;
        ua.x = ph2(a.x, a.y); ua.y = ph2(a.z, a.w);
        ub.x = ph2(b.x, b.y); ub.y = ph2(b.z, b.w);
        *(uint2*)(smu + UOFF_W1 + n * SROW + (k4 >> 1)) = ua;
        *(uint2*)(smu + UOFF_W2 + n * SROW + (k4 >> 1)) = ub;
    }
    __syncthreads();

    for (int tile = blockIdx.x * 4 + gid; tile < NTN64; tile += gridDim.x * 4) {
        const int m0 = tile * TILE64;

#pragma unroll
        for (int j = 0; j < 16; j++) {
            int i = lt + 128 * j;
            int row = i >> 5, k4 = (i & 31) << 2;
            size_t gm = (size_t)(m0 + row);
            float inv = 1.f / fmaxf(g_counts[gm], 1.f);
            float4 a = *(const float4*)(g_sums + gm * D + k4);
            float4 e = *(const float4*)(tgt_feat + gm * D + k4);
            uint2 u0, u1;
            u0.x = ph2(a.x * inv, a.y * inv);
            u0.y = ph2(a.z * inv, a.w * inv);
            u1.x = ph2(e.x, e.y);
            u1.y = ph2(e.z, e.w);
            *(uint2*)(smu + xa_off + row * SROW + (k4 >> 1)) = u0;
            *(uint2*)(smu + xb_off + row * SROW + (k4 >> 1)) = u1;
        }
        barg(gid);

        float acc[2][8][4];
#pragma unroll
        for (int mt = 0; mt < 2; mt++)
#pragma unroll
            for (int nt = 0; nt < 8; nt++)
#pragma unroll
                for (int j = 0; j < 4; j++) acc[mt][nt][j] = 0.f;

#pragma unroll
        for (int ks = 0; ks < 8; ks++) {
            uint32_t a0[2], a1[2], a2[2], a3[2];
#pragma unroll
            for (int mt = 0; mt < 2; mt++) {
                uint32_t ad = smb + (xa_off + (wr * 32 + mt * 16 + a_r) * SROW
                                     + ks * 8 + a_cu) * 4;
                ldsm_x4(a0[mt], a1[mt], a2[mt], a3[mt], ad);
            }
#pragma unroll
            for (int nt = 0; nt < 8; nt++) {
                uint32_t bd = smb + (UOFF_W1 + (wcol * 64 + nt * 8 + b_r) * SROW
                                     + ks * 8 + b_cu) * 4;
                uint32_t b0, b1;
                ldsm_x2(b0, b1, bd);
                mma16(acc[0][nt], a0[0], a1[0], a2[0], a3[0], b0, b1);
                mma16(acc[1][nt], a0[1], a1[1], a2[1], a3[1], b0, b1);
            }
        }
#pragma unroll
        for (int ks = 0; ks < 8; ks++) {
            uint32_t a0[2], a1[2], a2[2], a3[2];
#pragma unroll
            for (int mt = 0; mt < 2; mt++) {
                uint32_t ad = smb + (xb_off + (wr * 32 + mt * 16 + a_r) * SROW
                                     + ks * 8 + a_cu) * 4;
                ldsm_x4(a0[mt], a1[mt], a2[mt], a3[mt], ad);
            }
#pragma unroll
            for (int nt = 0; nt < 8; nt++) {
                uint32_t bd = smb + (UOFF_W2 + (wcol * 64 + nt * 8 + b_r) * SROW
                                     + ks * 8 + b_cu) * 4;
                uint32_t b0, b1;
                ldsm_x2(b0, b1, bd);
                mma16(acc[0][nt], a0[0], a1[0], a2[0], a3[0], b0, b1);
                mma16(acc[1][nt], a0[1], a1[1], a2[1], a3[1], b0, b1);
            }
        }

#pragma unroll
        for (int mt = 0; mt < 2; mt++) {
#pragma unroll
            for (int h = 0; h < 2; h++) {
                float s = 0.f, q = 0.f;
#pragma unroll
                for (int nt = 0; nt < 8; nt++) {
#pragma unroll
                    for (int j = 0; j < 2; j++) {
                        float v  = acc[mt][nt][h * 2 + j];
                        float sv = v / (1.f + __expf(-v));
                        acc[mt][nt][h * 2 + j] = sv;
                        s += sv; q += sv * sv;
                    }
                }
                s += __shfl_xor_sync(0xffffffffu, s, 1);
                s += __shfl_xor_sync(0xffffffffu, s, 2);
                q += __shfl_xor_sync(0xffffffffu, q, 1);
                q += __shfl_xor_sync(0xffffffffu, q, 2);
                if (t4 == 0) {
                    int row = wr * 32 + mt * 16 + h * 8 + g;
                    s_sum[wcol * 64 + row] = s;
                    s_sq[wcol * 64 + row]  = q;
                }
            }
        }
        barg(gid);

#pragma unroll
        for (int mt = 0; mt < 2; mt++) {
#pragma unroll
            for (int h = 0; h < 2; h++) {
                const int row = wr * 32 + mt * 16 + h * 8 + g;
                const float tsum = s_sum[row] + s_sum[64 + row];
                const float tsq  = s_sq[row]  + s_sq[64 + row];
                const float mean = tsum * (1.f / 128.f);
                const float inv  = rsqrtf(tsq * (1.f / 128.f) - mean * mean + 1e-5f);
                const size_t gm  = (size_t)(m0 + row);
                const float* __restrict__ er = tgt_feat + gm * D;
                float* __restrict__ orow = out + gm * D;
#pragma unroll
                for (int nt = 0; nt < 8; nt++) {
                    const int c = wcol * 64 + nt * 8 + t4 * 2;
                    float a0 = (acc[mt][nt][h * 2 + 0] - mean) * inv * s_g[c + 0] + s_b[c + 0];
                    float a1 = (acc[mt][nt][h * 2 + 1] - mean) * inv * s_g[c + 1] + s_b[c + 1];
                    float p0 = __shfl_xor_sync(0xffffffffu, a0, 1);
                    float p1 = __shfl_xor_sync(0xffffffffu, a1, 1);
                    if ((t4 & 1) == 0) {
                        float4 rs = *(const float4*)(er + c);
                        *(float4*)(orow + c) = make_float4(rs.x + a0, rs.y + a1,
                                                           rs.z + p0, rs.w + p1);
                    }
                }
            }
        }
    }
}

// ======================= launch =======================
extern "C" void kernel_launch(void* const* d_in, const int* in_sizes, int n_in,
                              void* d_out, int out_size) {
    const float* src_feat  = (const float*)d_in[0];
    const float* tgt_feat  = (const float*)d_in[1];
    const float* edge_feat = (const float*)d_in[2];
    const float* Ws2e      = (const float*)d_in[3];
    const float* We2e      = (const float*)d_in[4];
    const float* We2t      = (const float*)d_in[5];
    const float* Wt2t      = (const float*)d_in[6];
    const float* gamma1    = (const float*)d_in[7];
    const float* beta1     = (const float*)d_in[8];
    const float* gamma2    = (const float*)d_in[9];
    const float* beta2     = (const float*)d_in[10];
    const int*   src_idx   = (const int*)d_in[11];
    const int*   tgt_idx   = (const int*)d_in[12];
    float*       out       = (float*)d_out;

    cudaFuncSetAttribute(pre_kernel,
                         cudaFuncAttributeMaxDynamicSharedMemorySize, SMEM_BYTES);
    cudaFuncSetAttribute(edge_kernel,
                         cudaFuncAttributeMaxDynamicSharedMemorySize, SMEM_BYTES);
    cudaFuncSetAttribute(node_kernel,
                         cudaFuncAttributeMaxDynamicSharedMemorySize, SMEM_BYTES);

    zero_scratch_kernel<<<2048, 256>>>();

    pre_kernel<<<148, 512, SMEM_BYTES>>>(src_feat, tgt_feat, Ws2e);

    edge_kernel<<<148, 512, SMEM_BYTES>>>(
        edge_feat, We2e, gamma1, beta1, src_idx, tgt_idx, out);

    node_kernel<<<148, 512, SMEM_BYTES>>>(
        tgt_feat, We2t, Wt2t, gamma2, beta2, out + (size_t)N_EDGE * D);
}

// round 16
// speedup vs baseline: 1.1444x; 1.0643x over previous
#include <cuda_runtime.h>
#include <cuda_fp16.h>
#include <cstdint>

#define D 128
#define N_TGT 40000
#define N_SRC 40000
#define N_EDGE 640000
#define TILE64 64
#define NT64 (N_EDGE / TILE64)          // 10000 edge tiles
#define NTN64 (N_TGT / TILE64)          // 625 node tiles
#define NPRE (N_SRC + N_TGT)            // 80000 precompute rows
#define NTP64 (NPRE / TILE64)           // 1250 precompute tiles
#define SROW 68                          // u32 per fp16 smem row (64 data + 4 pad)
#define XBLK (TILE64 * SROW)             // 4352 u32 per X buffer

// ---------------- scratch ----------------
__device__ float  g_sums[(size_t)N_TGT * D];
__device__ float  g_counts[N_TGT];
__device__ __half g_ST[(size_t)NPRE * D];   // fp16! S1 rows [0,40k), T1 rows [40k,80k)

__global__ void zero_scratch_kernel() {
    const int n = N_TGT * D;
    const int total = n + N_TGT;
    for (int i = blockIdx.x * blockDim.x + threadIdx.x; i < total;
         i += gridDim.x * blockDim.x) {
        if (i < n) g_sums[i] = 0.f;
        else       g_counts[i - n] = 0.f;
    }
}

// ---------------- helpers ----------------
__device__ __forceinline__ uint32_t smem_addr_u32(const void* p) {
    uint32_t a;
    asm("{ .reg .u64 t; cvta.to.shared.u64 t, %1; cvt.u32.u64 %0, t; }"
        : "=r"(a) : "l"(p));
    return a;
}
__device__ __forceinline__ uint32_t ph2(float x, float y) {
    __half2 h = __floats2half2_rn(x, y);
    return *(uint32_t*)&h;
}
__device__ __forceinline__ void ldsm_x4(uint32_t& r0, uint32_t& r1,
                                        uint32_t& r2, uint32_t& r3, uint32_t a) {
    asm volatile("ldmatrix.sync.aligned.m8n8.x4.shared.b16 {%0,%1,%2,%3}, [%4];"
        : "=r"(r0), "=r"(r1), "=r"(r2), "=r"(r3) : "r"(a));
}
__device__ __forceinline__ void ldsm_x2(uint32_t& r0, uint32_t& r1, uint32_t a) {
    asm volatile("ldmatrix.sync.aligned.m8n8.x2.shared.b16 {%0,%1}, [%2];"
        : "=r"(r0), "=r"(r1) : "r"(a));
}
__device__ __forceinline__ void mma16(float* d, uint32_t a0, uint32_t a1,
                                      uint32_t a2, uint32_t a3,
                                      uint32_t b0, uint32_t b1) {
    asm volatile(
        "mma.sync.aligned.m16n8k16.row.col.f32.f16.f16.f32 "
        "{%0,%1,%2,%3},{%4,%5,%6,%7},{%8,%9},{%0,%1,%2,%3};"
        : "+f"(d[0]), "+f"(d[1]), "+f"(d[2]), "+f"(d[3])
        : "r"(a0), "r"(a1), "r"(a2), "r"(a3), "r"(b0), "r"(b1));
}
__device__ __forceinline__ void red_v4(float* p, float a, float b,
                                       float c, float d) {
    asm volatile("red.relaxed.gpu.global.add.v4.f32 [%0], {%1, %2, %3, %4};"
        :: "l"(p), "f"(a), "f"(b), "f"(c), "f"(d) : "memory");
}
__device__ __forceinline__ void barg(int gid) {
    asm volatile("bar.sync %0, 128;" :: "r"(gid + 1) : "memory");
}

// ---------------- smem layout (u32 offsets) ----------------
#define UOFF_W1  0
#define UOFF_W2  8704
#define UOFF_X   17408          // group g: XA = UOFF_X + g*2*XBLK, XB = XA + XBLK
#define UOFF_SUM 52224          // + g*128 floats
#define UOFF_SQ  52736          // + g*128 floats
#define UOFF_G   53248
#define UOFF_B   53376
#define SMEM_U32 53504
#define SMEM_BYTES (SMEM_U32 * 4)   // 214016

// ======================= PRE kernel: g_ST = [src;tgt] @ W1^T (fp16 out) ====
__global__ void __launch_bounds__(512, 1)
pre_kernel(const float* __restrict__ src_feat,
           const float* __restrict__ tgt_feat,
           const float* __restrict__ W1)
{
    extern __shared__ uint32_t smu[];
    const uint32_t smb = smem_addr_u32(smu);

    const int tid  = threadIdx.x;
    const int gid  = tid >> 7;
    const int lt   = tid & 127;
    const int wid  = lt >> 5;
    const int lane = tid & 31;
    const int g    = lane >> 2;
    const int t4   = lane & 3;
    const int wr   = wid & 1;
    const int wcol = wid >> 1;
    const uint32_t xa_off = UOFF_X + gid * 2 * XBLK;

    const int a_r  = (lane & 7) + ((lane >> 3) & 1) * 8;
    const int a_cu = ((lane >> 4) & 1) * 4;
    const int lb   = lane & 15;
    const int b_r  = lb & 7;
    const int b_cu = ((lb >> 3) & 1) * 4;

    for (int i = tid; i < 128 * 32; i += 512) {
        int n = i >> 5, k4 = (i & 31) << 2;
        float4 a = *(const float4*)(W1 + n * D + k4);
        uint2 ua;
        ua.x = ph2(a.x, a.y); ua.y = ph2(a.z, a.w);
        *(uint2*)(smu + UOFF_W1 + n * SROW + (k4 >> 1)) = ua;
    }
    __syncthreads();

    for (int tile = blockIdx.x * 4 + gid; tile < NTP64; tile += gridDim.x * 4) {
        const int r0 = tile * TILE64;

#pragma unroll
        for (int j = 0; j < 16; j++) {
            int i = lt + 128 * j;
            int row = i >> 5, k4 = (i & 31) << 2;
            int r = r0 + row;
            const float* p = (r < N_SRC) ? (src_feat + (size_t)r * D + k4)
                                         : (tgt_feat + (size_t)(r - N_SRC) * D + k4);
            float4 v = *(const float4*)p;
            uint2 u;
            u.x = ph2(v.x, v.y); u.y = ph2(v.z, v.w);
            *(uint2*)(smu + xa_off + row * SROW + (k4 >> 1)) = u;
        }
        barg(gid);

        float acc[2][8][4];
#pragma unroll
        for (int mt = 0; mt < 2; mt++)
#pragma unroll
            for (int nt = 0; nt < 8; nt++)
#pragma unroll
                for (int j = 0; j < 4; j++) acc[mt][nt][j] = 0.f;

#pragma unroll
        for (int ks = 0; ks < 8; ks++) {
            uint32_t a0[2], a1[2], a2[2], a3[2];
#pragma unroll
            for (int mt = 0; mt < 2; mt++) {
                uint32_t ad = smb + (xa_off + (wr * 32 + mt * 16 + a_r) * SROW
                                     + ks * 8 + a_cu) * 4;
                ldsm_x4(a0[mt], a1[mt], a2[mt], a3[mt], ad);
            }
#pragma unroll
            for (int nt = 0; nt < 8; nt++) {
                uint32_t bd = smb + (UOFF_W1 + (wcol * 64 + nt * 8 + b_r) * SROW
                                     + ks * 8 + b_cu) * 4;
                uint32_t b0, b1;
                ldsm_x2(b0, b1, bd);
                mma16(acc[0][nt], a0[0], a1[0], a2[0], a3[0], b0, b1);
                mma16(acc[1][nt], a0[1], a1[1], a2[1], a3[1], b0, b1);
            }
        }
        barg(gid);   // all ldsm of XA done before next staging

#pragma unroll
        for (int mt = 0; mt < 2; mt++) {
#pragma unroll
            for (int h = 0; h < 2; h++) {
                const int row = wr * 32 + mt * 16 + h * 8 + g;
                __half* __restrict__ orow = g_ST + (size_t)(r0 + row) * D;
#pragma unroll
                for (int nt = 0; nt < 8; nt++) {
                    const int c = wcol * 64 + nt * 8 + t4 * 2;
                    float a0 = acc[mt][nt][h * 2 + 0];
                    float a1 = acc[mt][nt][h * 2 + 1];
                    float p0 = __shfl_xor_sync(0xffffffffu, a0, 1);
                    float p1 = __shfl_xor_sync(0xffffffffu, a1, 1);
                    if ((t4 & 1) == 0) {
                        uint2 u;
                        u.x = ph2(a0, a1);
                        u.y = ph2(p0, p1);
                        *(uint2*)(orow + c) = u;   // 4 fp16 cols, 8B aligned
                    }
                }
            }
        }
    }
}

// ======================= EDGE kernel (1 MMA pass + fp16 gathered pass-1) ===
__global__ void __launch_bounds__(512, 1)
edge_kernel(const float* __restrict__ edge_feat,
            const float* __restrict__ W2,
            const float* __restrict__ gamma,
            const float* __restrict__ beta,
            const int*   __restrict__ src_idx,
            const int*   __restrict__ tgt_idx,
            float*       __restrict__ out)
{
    extern __shared__ uint32_t smu[];
    const uint32_t smb = smem_addr_u32(smu);

    const int tid  = threadIdx.x;
    const int gid  = tid >> 7;
    const int lt   = tid & 127;
    const int wid  = lt >> 5;
    const int lane = tid & 31;
    const int g    = lane >> 2;
    const int t4   = lane & 3;
    const int wr   = wid & 1;
    const int wcol = wid >> 1;

    float* s_sum = (float*)(smu + UOFF_SUM + gid * 128);
    float* s_sq  = (float*)(smu + UOFF_SQ  + gid * 128);
    float* s_g = (float*)(smu + UOFF_G);
    float* s_b = (float*)(smu + UOFF_B);
    const uint32_t xa_off = UOFF_X + gid * 2 * XBLK;   // fp16 pass-1 sum (LDS)
    const uint32_t xb_off = xa_off + XBLK;             // fp16 edge rows

    const int a_r  = (lane & 7) + ((lane >> 3) & 1) * 8;
    const int a_cu = ((lane >> 4) & 1) * 4;
    const int lb   = lane & 15;
    const int b_r  = lb & 7;
    const int b_cu = ((lb >> 3) & 1) * 4;

    if (tid < 128) { s_g[tid] = gamma[tid]; s_b[tid] = beta[tid]; }

    // stage W2 (fp16)
    for (int i = tid; i < 128 * 32; i += 512) {
        int n = i >> 5, k4 = (i & 31) << 2;
        float4 b = *(const float4*)(W2 + n * D + k4);
        uint2 ub;
        ub.x = ph2(b.x, b.y); ub.y = ph2(b.z, b.w);
        *(uint2*)(smu + UOFF_W2 + n * SROW + (k4 >> 1)) = ub;
    }
    __syncthreads();

    for (int tile = blockIdx.x * 4 + gid; tile < NT64; tile += gridDim.x * 4) {
        const int m0 = tile * TILE64;

        // ---- stage XA = S1[si]+T1[ti] (fp16 adds), XB = edge (fp16) ----
#pragma unroll
        for (int j = 0; j < 16; j++) {
            int i = lt + 128 * j;
            int row = i >> 5, k4 = (i & 31) << 2;
            int si = src_idx[m0 + row];
            int ti = tgt_idx[m0 + row];
            uint2 ua = *(const uint2*)(g_ST + (size_t)si * D + k4);
            uint2 ub = *(const uint2*)(g_ST + (size_t)(N_SRC + ti) * D + k4);
            float4 e = *(const float4*)(edge_feat + (size_t)(m0 + row) * D + k4);
            uint2 u0, u1;
            __half2 s0 = __hadd2(*reinterpret_cast<__half2*>(&ua.x),
                                 *reinterpret_cast<__half2*>(&ub.x));
            __half2 s1 = __hadd2(*reinterpret_cast<__half2*>(&ua.y),
                                 *reinterpret_cast<__half2*>(&ub.y));
            u0.x = *(uint32_t*)&s0;
            u0.y = *(uint32_t*)&s1;
            u1.x = ph2(e.x, e.y);
            u1.y = ph2(e.z, e.w);
            *(uint2*)(smu + xa_off + row * SROW + (k4 >> 1)) = u0;
            *(uint2*)(smu + xb_off + row * SROW + (k4 >> 1)) = u1;
        }
        barg(gid);

        float acc[2][8][4];
#pragma unroll
        for (int mt = 0; mt < 2; mt++)
#pragma unroll
            for (int nt = 0; nt < 8; nt++)
#pragma unroll
                for (int j = 0; j < 4; j++) acc[mt][nt][j] = 0.f;

        // ---- single MMA pass: acc = XB @ W2^T ----
#pragma unroll
        for (int ks = 0; ks < 8; ks++) {
            uint32_t a0[2], a1[2], a2[2], a3[2];
#pragma unroll
            for (int mt = 0; mt < 2; mt++) {
                uint32_t ad = smb + (xb_off + (wr * 32 + mt * 16 + a_r) * SROW
                                     + ks * 8 + a_cu) * 4;
                ldsm_x4(a0[mt], a1[mt], a2[mt], a3[mt], ad);
            }
#pragma unroll
            for (int nt = 0; nt < 8; nt++) {
                uint32_t bd = smb + (UOFF_W2 + (wcol * 64 + nt * 8 + b_r) * SROW
                                     + ks * 8 + b_cu) * 4;
                uint32_t b0, b1;
                ldsm_x2(b0, b1, bd);
                mma16(acc[0][nt], a0[0], a1[0], a2[0], a3[0], b0, b1);
                mma16(acc[1][nt], a0[1], a1[1], a2[1], a3[1], b0, b1);
            }
        }

        // ---- add gathered pass-1 (XA), then silu + LN partials ----
#pragma unroll
        for (int mt = 0; mt < 2; mt++) {
#pragma unroll
            for (int h = 0; h < 2; h++) {
                const int row = wr * 32 + mt * 16 + h * 8 + g;
                float s = 0.f, q = 0.f;
#pragma unroll
                for (int nt = 0; nt < 8; nt++) {
                    const int c = wcol * 64 + nt * 8 + t4 * 2;
                    uint32_t u = smu[xa_off + row * SROW + (c >> 1)];
                    __half2 hv = *reinterpret_cast<__half2*>(&u);
                    float2 f = __half22float2(hv);
#pragma unroll
                    for (int j = 0; j < 2; j++) {
                        float v  = acc[mt][nt][h * 2 + j] + (j ? f.y : f.x);
                        float sv = v / (1.f + __expf(-v));
                        acc[mt][nt][h * 2 + j] = sv;
                        s += sv; q += sv * sv;
                    }
                }
                s += __shfl_xor_sync(0xffffffffu, s, 1);
                s += __shfl_xor_sync(0xffffffffu, s, 2);
                q += __shfl_xor_sync(0xffffffffu, q, 1);
                q += __shfl_xor_sync(0xffffffffu, q, 2);
                if (t4 == 0) {
                    s_sum[wcol * 64 + row] = s;
                    s_sq[wcol * 64 + row]  = q;
                }
            }
        }
        barg(gid);

        // ---- LN + residual(from fp16 XB in smem) + out + scatter ----
#pragma unroll
        for (int mt = 0; mt < 2; mt++) {
#pragma unroll
            for (int h = 0; h < 2; h++) {
                const int row = wr * 32 + mt * 16 + h * 8 + g;
                const float tsum = s_sum[row] + s_sum[64 + row];
                const float tsq  = s_sq[row]  + s_sq[64 + row];
                const float mean = tsum * (1.f / 128.f);
                const float inv  = rsqrtf(tsq * (1.f / 128.f) - mean * mean + 1e-5f);
                const int    t   = tgt_idx[m0 + row];
                const size_t gm  = (size_t)(m0 + row);
                float* __restrict__ srow = g_sums + (size_t)t * D;
                float* __restrict__ orow = out + gm * D;
#pragma unroll
                for (int nt = 0; nt < 8; nt++) {
                    const int c = wcol * 64 + nt * 8 + t4 * 2;
                    float a0 = (acc[mt][nt][h * 2 + 0] - mean) * inv * s_g[c + 0] + s_b[c + 0];
                    float a1 = (acc[mt][nt][h * 2 + 1] - mean) * inv * s_g[c + 1] + s_b[c + 1];
                    float p0 = __shfl_xor_sync(0xffffffffu, a0, 1);
                    float p1 = __shfl_xor_sync(0xffffffffu, a1, 1);
                    if ((t4 & 1) == 0) {
                        uint2 ue = *(const uint2*)(smu + xb_off + row * SROW + (c >> 1));
                        float2 e0 = __half22float2(*reinterpret_cast<__half2*>(&ue.x));
                        float2 e1 = __half22float2(*reinterpret_cast<__half2*>(&ue.y));
                        *(float4*)(orow + c) = make_float4(e0.x + a0, e0.y + a1,
                                                           e1.x + p0, e1.y + p1);
                        red_v4(srow + c, a0, a1, p0, p1);
                    }
                }
                if (wcol == 0 && t4 == 0) atomicAdd(g_counts + t, 1.f);
            }
        }
        barg(gid);   // XB read in epilogue: protect before next staging
    }
}

// ======================= NODE kernel (two MMA passes, as R12) ==============
__global__ void __launch_bounds__(512, 1)
node_kernel(const float* __restrict__ tgt_feat,
            const float* __restrict__ W1,       // We2t
            const float* __restrict__ W2,       // Wt2t
            const float* __restrict__ gamma,
            const float* __restrict__ beta,
            float*       __restrict__ out)
{
    extern __shared__ uint32_t smu[];
    const uint32_t smb = smem_addr_u32(smu);

    const int tid  = threadIdx.x;
    const int gid  = tid >> 7;
    const int lt   = tid & 127;
    const int wid  = lt >> 5;
    const int lane = tid & 31;
    const int g    = lane >> 2;
    const int t4   = lane & 3;
    const int wr   = wid & 1;
    const int wcol = wid >> 1;

    float* s_sum = (float*)(smu + UOFF_SUM + gid * 128);
    float* s_sq  = (float*)(smu + UOFF_SQ  + gid * 128);
    float* s_g   = (float*)(smu + UOFF_G);
    float* s_b   = (float*)(smu + UOFF_B);
    const uint32_t xa_off = UOFF_X + gid * 2 * XBLK;
    const uint32_t xb_off = xa_off + XBLK;

    const int a_r  = (lane & 7) + ((lane >> 3) & 1) * 8;
    const int a_cu = ((lane >> 4) & 1) * 4;
    const int lb   = lane & 15;
    const int b_r  = lb & 7;
    const int b_cu = ((lb >> 3) & 1) * 4;

    if (tid < 128) { s_g[tid] = gamma[tid]; s_b[tid] = beta[tid]; }

    for (int i = tid; i < 128 * 32; i += 512) {
        int n = i >> 5, k4 = (i & 31) << 2;
        float4 a = *(const float4*)(W1 + n * D + k4);
        float4 b = *(const float4*)(W2 + n * D + k4);
        uint2 ua, ub;
        ua.x = ph2(a.x, a.y); ua.y = ph2(a.z, a.w);
        ub.x = ph2(b.x, b.y); ub.y = ph2(b.z, b.w);
        *(uint2*)(smu + UOFF_W1 + n * SROW + (k4 >> 1)) = ua;
        *(uint2*)(smu + UOFF_W2 + n * SROW + (k4 >> 1)) = ub;
    }
    __syncthreads();

    for (int tile = blockIdx.x * 4 + gid; tile < NTN64; tile += gridDim.x * 4) {
        const int m0 = tile * TILE64;

#pragma unroll
        for (int j = 0; j < 16; j++) {
            int i = lt + 128 * j;
            int row = i >> 5, k4 = (i & 31) << 2;
            size_t gm = (size_t)(m0 + row);
            float inv = 1.f / fmaxf(g_counts[gm], 1.f);
            float4 a = *(const float4*)(g_sums + gm * D + k4);
            float4 e = *(const float4*)(tgt_feat + gm * D + k4);
            uint2 u0, u1;
            u0.x = ph2(a.x * inv, a.y * inv);
            u0.y = ph2(a.z * inv, a.w * inv);
            u1.x = ph2(e.x, e.y);
            u1.y = ph2(e.z, e.w);
            *(uint2*)(smu + xa_off + row * SROW + (k4 >> 1)) = u0;
            *(uint2*)(smu + xb_off + row * SROW + (k4 >> 1)) = u1;
        }
        barg(gid);

        float acc[2][8][4];
#pragma unroll
        for (int mt = 0; mt < 2; mt++)
#pragma unroll
            for (int nt = 0; nt < 8; nt++)
#pragma unroll
                for (int j = 0; j < 4; j++) acc[mt][nt][j] = 0.f;

#pragma unroll
        for (int ks = 0; ks < 8; ks++) {
            uint32_t a0[2], a1[2], a2[2], a3[2];
#pragma unroll
            for (int mt = 0; mt < 2; mt++) {
                uint32_t ad = smb + (xa_off + (wr * 32 + mt * 16 + a_r) * SROW
                                     + ks * 8 + a_cu) * 4;
                ldsm_x4(a0[mt], a1[mt], a2[mt], a3[mt], ad);
            }
#pragma unroll
            for (int nt = 0; nt < 8; nt++) {
                uint32_t bd = smb + (UOFF_W1 + (wcol * 64 + nt * 8 + b_r) * SROW
                                     + ks * 8 + b_cu) * 4;
                uint32_t b0, b1;
                ldsm_x2(b0, b1, bd);
                mma16(acc[0][nt], a0[0], a1[0], a2[0], a3[0], b0, b1);
                mma16(acc[1][nt], a0[1], a1[1], a2[1], a3[1], b0, b1);
            }
        }
#pragma unroll
        for (int ks = 0; ks < 8; ks++) {
            uint32_t a0[2], a1[2], a2[2], a3[2];
#pragma unroll
            for (int mt = 0; mt < 2; mt++) {
                uint32_t ad = smb + (xb_off + (wr * 32 + mt * 16 + a_r) * SROW
                                     + ks * 8 + a_cu) * 4;
                ldsm_x4(a0[mt], a1[mt], a2[mt], a3[mt], ad);
            }
#pragma unroll
            for (int nt = 0; nt < 8; nt++) {
                uint32_t bd = smb + (UOFF_W2 + (wcol * 64 + nt * 8 + b_r) * SROW
                                     + ks * 8 + b_cu) * 4;
                uint32_t b0, b1;
                ldsm_x2(b0, b1, bd);
                mma16(acc[0][nt], a0[0], a1[0], a2[0], a3[0], b0, b1);
                mma16(acc[1][nt], a0[1], a1[1], a2[1], a3[1], b0, b1);
            }
        }

#pragma unroll
        for (int mt = 0; mt < 2; mt++) {
#pragma unroll
            for (int h = 0; h < 2; h++) {
                float s = 0.f, q = 0.f;
#pragma unroll
                for (int nt = 0; nt < 8; nt++) {
#pragma unroll
                    for (int j = 0; j < 2; j++) {
                        float v  = acc[mt][nt][h * 2 + j];
                        float sv = v / (1.f + __expf(-v));
                        acc[mt][nt][h * 2 + j] = sv;
                        s += sv; q += sv * sv;
                    }
                }
                s += __shfl_xor_sync(0xffffffffu, s, 1);
                s += __shfl_xor_sync(0xffffffffu, s, 2);
                q += __shfl_xor_sync(0xffffffffu, q, 1);
                q += __shfl_xor_sync(0xffffffffu, q, 2);
                if (t4 == 0) {
                    int row = wr * 32 + mt * 16 + h * 8 + g;
                    s_sum[wcol * 64 + row] = s;
                    s_sq[wcol * 64 + row]  = q;
                }
            }
        }
        barg(gid);

#pragma unroll
        for (int mt = 0; mt < 2; mt++) {
#pragma unroll
            for (int h = 0; h < 2; h++) {
                const int row = wr * 32 + mt * 16 + h * 8 + g;
                const float tsum = s_sum[row] + s_sum[64 + row];
                const float tsq  = s_sq[row]  + s_sq[64 + row];
                const float mean = tsum * (1.f / 128.f);
                const float inv  = rsqrtf(tsq * (1.f / 128.f) - mean * mean + 1e-5f);
                const size_t gm  = (size_t)(m0 + row);
                const float* __restrict__ er = tgt_feat + gm * D;
                float* __restrict__ orow = out + gm * D;
#pragma unroll
                for (int nt = 0; nt < 8; nt++) {
                    const int c = wcol * 64 + nt * 8 + t4 * 2;
                    float a0 = (acc[mt][nt][h * 2 + 0] - mean) * inv * s_g[c + 0] + s_b[c + 0];
                    float a1 = (acc[mt][nt][h * 2 + 1] - mean) * inv * s_g[c + 1] + s_b[c + 1];
                    float p0 = __shfl_xor_sync(0xffffffffu, a0, 1);
                    float p1 = __shfl_xor_sync(0xffffffffu, a1, 1);
                    if ((t4 & 1) == 0) {
                        float4 rs = *(const float4*)(er + c);
                        *(float4*)(orow + c) = make_float4(rs.x + a0, rs.y + a1,
                                                           rs.z + p0, rs.w + p1);
                    }
                }
            }
        }
    }
}

// ======================= launch =======================
extern "C" void kernel_launch(void* const* d_in, const int* in_sizes, int n_in,
                              void* d_out, int out_size) {
    const float* src_feat  = (const float*)d_in[0];
    const float* tgt_feat  = (const float*)d_in[1];
    const float* edge_feat = (const float*)d_in[2];
    const float* Ws2e      = (const float*)d_in[3];
    const float* We2e      = (const float*)d_in[4];
    const float* We2t      = (const float*)d_in[5];
    const float* Wt2t      = (const float*)d_in[6];
    const float* gamma1    = (const float*)d_in[7];
    const float* beta1     = (const float*)d_in[8];
    const float* gamma2    = (const float*)d_in[9];
    const float* beta2     = (const float*)d_in[10];
    const int*   src_idx   = (const int*)d_in[11];
    const int*   tgt_idx   = (const int*)d_in[12];
    float*       out       = (float*)d_out;

    cudaFuncSetAttribute(pre_kernel,
                         cudaFuncAttributeMaxDynamicSharedMemorySize, SMEM_BYTES);
    cudaFuncSetAttribute(edge_kernel,
                         cudaFuncAttributeMaxDynamicSharedMemorySize, SMEM_BYTES);
    cudaFuncSetAttribute(node_kernel,
                         cudaFuncAttributeMaxDynamicSharedMemorySize, SMEM_BYTES);

    zero_scratch_kernel<<<2048, 256>>>();

    pre_kernel<<<148, 512, SMEM_BYTES>>>(src_feat, tgt_feat, Ws2e);

    edge_kernel<<<148, 512, SMEM_BYTES>>>(
        edge_feat, We2e, gamma1, beta1, src_idx, tgt_idx, out);

    node_kernel<<<148, 512, SMEM_BYTES>>>(
        tgt_feat, We2t, Wt2t, gamma2, beta2, out + (size_t)N_EDGE * D);
}

// round 17
// speedup vs baseline: 1.2870x; 1.1246x over previous
#include <cuda_runtime.h>
#include <cuda_fp16.h>
#include <cstdint>

#define D 128
#define N_TGT 40000
#define N_SRC 40000
#define N_EDGE 640000
#define TILE64 64
#define NT64 (N_EDGE / TILE64)          // 10000 edge tiles
#define NTN64 (N_TGT / TILE64)          // 625 node tiles
#define NPRE (N_SRC + N_TGT)            // 80000 precompute rows
#define NTP64 (NPRE / TILE64)           // 1250 precompute tiles
#define SROW 68                          // u32 per fp16 smem row (64 data + 4 pad)
#define XBLK (TILE64 * SROW)             // 4352 u32 per X buffer

// ---------------- scratch ----------------
__device__ float  g_sums[(size_t)N_TGT * D];
__device__ float  g_counts[N_TGT];
__device__ __half g_ST[(size_t)NPRE * D];   // fp16 S1 rows [0,40k), T1 rows [40k,80k)

__global__ void zero_scratch_kernel() {
    const int n = N_TGT * D;
    const int total = n + N_TGT;
    for (int i = blockIdx.x * blockDim.x + threadIdx.x; i < total;
         i += gridDim.x * blockDim.x) {
        if (i < n) g_sums[i] = 0.f;
        else       g_counts[i - n] = 0.f;
    }
}

// ---------------- helpers ----------------
__device__ __forceinline__ uint32_t smem_addr_u32(const void* p) {
    uint32_t a;
    asm("{ .reg .u64 t; cvta.to.shared.u64 t, %1; cvt.u32.u64 %0, t; }"
        : "=r"(a) : "l"(p));
    return a;
}
__device__ __forceinline__ uint32_t ph2(float x, float y) {
    __half2 h = __floats2half2_rn(x, y);
    return *(uint32_t*)&h;
}
__device__ __forceinline__ float silu_fast(float v) {
    return __fdividef(v, 1.f + __expf(-v));
}
__device__ __forceinline__ void ldsm_x4(uint32_t& r0, uint32_t& r1,
                                        uint32_t& r2, uint32_t& r3, uint32_t a) {
    asm volatile("ldmatrix.sync.aligned.m8n8.x4.shared.b16 {%0,%1,%2,%3}, [%4];"
        : "=r"(r0), "=r"(r1), "=r"(r2), "=r"(r3) : "r"(a));
}
__device__ __forceinline__ void mma16(float* d, uint32_t a0, uint32_t a1,
                                      uint32_t a2, uint32_t a3,
                                      uint32_t b0, uint32_t b1) {
    asm volatile(
        "mma.sync.aligned.m16n8k16.row.col.f32.f16.f16.f32 "
        "{%0,%1,%2,%3},{%4,%5,%6,%7},{%8,%9},{%0,%1,%2,%3};"
        : "+f"(d[0]), "+f"(d[1]), "+f"(d[2]), "+f"(d[3])
        : "r"(a0), "r"(a1), "r"(a2), "r"(a3), "r"(b0), "r"(b1));
}
__device__ __forceinline__ void red_v4(float* p, float a, float b,
                                       float c, float d) {
    asm volatile("red.relaxed.gpu.global.add.v4.f32 [%0], {%1, %2, %3, %4};"
        :: "l"(p), "f"(a), "f"(b), "f"(c), "f"(d) : "memory");
}
__device__ __forceinline__ void barg(int gid) {
    asm volatile("bar.sync %0, 128;" :: "r"(gid + 1) : "memory");
}

// ---------------- smem layout (u32 offsets) ----------------
#define UOFF_W1  0
#define UOFF_W2  8704
#define UOFF_X   17408          // group g: XA = UOFF_X + g*2*XBLK, XB = XA + XBLK
#define UOFF_SUM 52224          // + g*128 floats
#define UOFF_SQ  52736          // + g*128 floats
#define UOFF_G   53248
#define UOFF_B   53376
#define SMEM_U32 53504
#define SMEM_BYTES (SMEM_U32 * 4)   // 214016

// ======================= PRE kernel: g_ST = [src;tgt] @ W1^T (fp16 out) ====
__global__ void __launch_bounds__(512, 1)
pre_kernel(const float* __restrict__ src_feat,
           const float* __restrict__ tgt_feat,
           const float* __restrict__ W1)
{
    extern __shared__ uint32_t smu[];
    const uint32_t smb = smem_addr_u32(smu);

    const int tid  = threadIdx.x;
    const int gid  = tid >> 7;
    const int lt   = tid & 127;
    const int wid  = lt >> 5;
    const int lane = tid & 31;
    const int t4   = lane & 3;
    const int g    = lane >> 2;
    const int wr   = wid & 1;
    const int wcol = wid >> 1;
    const uint32_t xa_off = UOFF_X + gid * 2 * XBLK;

    const int a_r  = (lane & 7) + ((lane >> 3) & 1) * 8;
    const int a_cu = ((lane >> 4) & 1) * 4;
    // B-pair ldsm_x4 lane geometry: bit4 -> nt offset, bit3 -> k-half
    const int bq_r  = (lane & 7) + ((lane >> 4) & 1) * 8;
    const int bq_cu = ((lane >> 3) & 1) * 4;

    for (int i = tid; i < 128 * 32; i += 512) {
        int n = i >> 5, k4 = (i & 31) << 2;
        float4 a = *(const float4*)(W1 + n * D + k4);
        uint2 ua;
        ua.x = ph2(a.x, a.y); ua.y = ph2(a.z, a.w);
        *(uint2*)(smu + UOFF_W1 + n * SROW + (k4 >> 1)) = ua;
    }
    __syncthreads();

    for (int tile = blockIdx.x * 4 + gid; tile < NTP64; tile += gridDim.x * 4) {
        const int r0 = tile * TILE64;

#pragma unroll
        for (int j = 0; j < 16; j++) {
            int i = lt + 128 * j;
            int row = i >> 5, k4 = (i & 31) << 2;
            int r = r0 + row;
            const float* p = (r < N_SRC) ? (src_feat + (size_t)r * D + k4)
                                         : (tgt_feat + (size_t)(r - N_SRC) * D + k4);
            float4 v = *(const float4*)p;
            uint2 u;
            u.x = ph2(v.x, v.y); u.y = ph2(v.z, v.w);
            *(uint2*)(smu + xa_off + row * SROW + (k4 >> 1)) = u;
        }
        barg(gid);

        float acc[2][8][4];
#pragma unroll
        for (int mt = 0; mt < 2; mt++)
#pragma unroll
            for (int nt = 0; nt < 8; nt++)
#pragma unroll
                for (int j = 0; j < 4; j++) acc[mt][nt][j] = 0.f;

#pragma unroll
        for (int ks = 0; ks < 8; ks++) {
            uint32_t a0[2], a1[2], a2[2], a3[2];
#pragma unroll
            for (int mt = 0; mt < 2; mt++) {
                uint32_t ad = smb + (xa_off + (wr * 32 + mt * 16 + a_r) * SROW
                                     + ks * 8 + a_cu) * 4;
                ldsm_x4(a0[mt], a1[mt], a2[mt], a3[mt], ad);
            }
#pragma unroll
            for (int nt = 0; nt < 8; nt += 2) {
                uint32_t b0, b1, b2, b3;
                uint32_t bd = smb + (UOFF_W1 + (wcol * 64 + nt * 8 + bq_r) * SROW
                                     + ks * 8 + bq_cu) * 4;
                ldsm_x4(b0, b1, b2, b3, bd);
                mma16(acc[0][nt],     a0[0], a1[0], a2[0], a3[0], b0, b1);
                mma16(acc[1][nt],     a0[1], a1[1], a2[1], a3[1], b0, b1);
                mma16(acc[0][nt + 1], a0[0], a1[0], a2[0], a3[0], b2, b3);
                mma16(acc[1][nt + 1], a0[1], a1[1], a2[1], a3[1], b2, b3);
            }
        }
        barg(gid);   // all ldsm of XA done before next staging

#pragma unroll
        for (int mt = 0; mt < 2; mt++) {
#pragma unroll
            for (int h = 0; h < 2; h++) {
                const int row = wr * 32 + mt * 16 + h * 8 + g;
                __half* __restrict__ orow = g_ST + (size_t)(r0 + row) * D;
#pragma unroll
                for (int nt = 0; nt < 8; nt++) {
                    const int c = wcol * 64 + nt * 8 + t4 * 2;
                    float a0 = acc[mt][nt][h * 2 + 0];
                    float a1 = acc[mt][nt][h * 2 + 1];
                    float p0 = __shfl_xor_sync(0xffffffffu, a0, 1);
                    float p1 = __shfl_xor_sync(0xffffffffu, a1, 1);
                    if ((t4 & 1) == 0) {
                        uint2 u;
                        u.x = ph2(a0, a1);
                        u.y = ph2(p0, p1);
                        *(uint2*)(orow + c) = u;
                    }
                }
            }
        }
    }
}

// ======================= EDGE kernel (1 MMA pass + fp16 gathered pass-1) ===
__global__ void __launch_bounds__(512, 1)
edge_kernel(const float* __restrict__ edge_feat,
            const float* __restrict__ W2,
            const float* __restrict__ gamma,
            const float* __restrict__ beta,
            const int*   __restrict__ src_idx,
            const int*   __restrict__ tgt_idx,
            float*       __restrict__ out)
{
    extern __shared__ uint32_t smu[];
    const uint32_t smb = smem_addr_u32(smu);

    const int tid  = threadIdx.x;
    const int gid  = tid >> 7;
    const int lt   = tid & 127;
    const int wid  = lt >> 5;
    const int lane = tid & 31;
    const int g    = lane >> 2;
    const int t4   = lane & 3;
    const int wr   = wid & 1;
    const int wcol = wid >> 1;

    float* s_sum = (float*)(smu + UOFF_SUM + gid * 128);
    float* s_sq  = (float*)(smu + UOFF_SQ  + gid * 128);
    float* s_g = (float*)(smu + UOFF_G);
    float* s_b = (float*)(smu + UOFF_B);
    const uint32_t xa_off = UOFF_X + gid * 2 * XBLK;   // fp16 pass-1 sum (LDS)
    const uint32_t xb_off = xa_off + XBLK;             // fp16 edge rows

    const int a_r  = (lane & 7) + ((lane >> 3) & 1) * 8;
    const int a_cu = ((lane >> 4) & 1) * 4;
    const int bq_r  = (lane & 7) + ((lane >> 4) & 1) * 8;
    const int bq_cu = ((lane >> 3) & 1) * 4;

    if (tid < 128) { s_g[tid] = gamma[tid]; s_b[tid] = beta[tid]; }

    // stage W2 (fp16)
    for (int i = tid; i < 128 * 32; i += 512) {
        int n = i >> 5, k4 = (i & 31) << 2;
        float4 b = *(const float4*)(W2 + n * D + k4);
        uint2 ub;
        ub.x = ph2(b.x, b.y); ub.y = ph2(b.z, b.w);
        *(uint2*)(smu + UOFF_W2 + n * SROW + (k4 >> 1)) = ub;
    }
    __syncthreads();

    for (int tile = blockIdx.x * 4 + gid; tile < NT64; tile += gridDim.x * 4) {
        const int m0 = tile * TILE64;

        // ---- stage XA = S1[si]+T1[ti] (fp16 adds), XB = edge (fp16) ----
#pragma unroll
        for (int j = 0; j < 16; j++) {
            int i = lt + 128 * j;
            int row = i >> 5, k4 = (i & 31) << 2;
            int si = src_idx[m0 + row];
            int ti = tgt_idx[m0 + row];
            uint2 ua = *(const uint2*)(g_ST + (size_t)si * D + k4);
            uint2 ub = *(const uint2*)(g_ST + (size_t)(N_SRC + ti) * D + k4);
            float4 e = *(const float4*)(edge_feat + (size_t)(m0 + row) * D + k4);
            uint2 u0, u1;
            __half2 s0 = __hadd2(*reinterpret_cast<__half2*>(&ua.x),
                                 *reinterpret_cast<__half2*>(&ub.x));
            __half2 s1 = __hadd2(*reinterpret_cast<__half2*>(&ua.y),
                                 *reinterpret_cast<__half2*>(&ub.y));
            u0.x = *(uint32_t*)&s0;
            u0.y = *(uint32_t*)&s1;
            u1.x = ph2(e.x, e.y);
            u1.y = ph2(e.z, e.w);
            *(uint2*)(smu + xa_off + row * SROW + (k4 >> 1)) = u0;
            *(uint2*)(smu + xb_off + row * SROW + (k4 >> 1)) = u1;
        }
        barg(gid);

        float acc[2][8][4];
#pragma unroll
        for (int mt = 0; mt < 2; mt++)
#pragma unroll
            for (int nt = 0; nt < 8; nt++)
#pragma unroll
                for (int j = 0; j < 4; j++) acc[mt][nt][j] = 0.f;

        // ---- single MMA pass: acc = XB @ W2^T ----
#pragma unroll
        for (int ks = 0; ks < 8; ks++) {
            uint32_t a0[2], a1[2], a2[2], a3[2];
#pragma unroll
            for (int mt = 0; mt < 2; mt++) {
                uint32_t ad = smb + (xb_off + (wr * 32 + mt * 16 + a_r) * SROW
                                     + ks * 8 + a_cu) * 4;
                ldsm_x4(a0[mt], a1[mt], a2[mt], a3[mt], ad);
            }
#pragma unroll
            for (int nt = 0; nt < 8; nt += 2) {
                uint32_t b0, b1, b2, b3;
                uint32_t bd = smb + (UOFF_W2 + (wcol * 64 + nt * 8 + bq_r) * SROW
                                     + ks * 8 + bq_cu) * 4;
                ldsm_x4(b0, b1, b2, b3, bd);
                mma16(acc[0][nt],     a0[0], a1[0], a2[0], a3[0], b0, b1);
                mma16(acc[1][nt],     a0[1], a1[1], a2[1], a3[1], b0, b1);
                mma16(acc[0][nt + 1], a0[0], a1[0], a2[0], a3[0], b2, b3);
                mma16(acc[1][nt + 1], a0[1], a1[1], a2[1], a3[1], b2, b3);
            }
        }

        // ---- add gathered pass-1 (XA), then silu + LN partials ----
#pragma unroll
        for (int mt = 0; mt < 2; mt++) {
#pragma unroll
            for (int h = 0; h < 2; h++) {
                const int row = wr * 32 + mt * 16 + h * 8 + g;
                float s = 0.f, q = 0.f;
#pragma unroll
                for (int nt = 0; nt < 8; nt++) {
                    const int c = wcol * 64 + nt * 8 + t4 * 2;
                    uint32_t u = smu[xa_off + row * SROW + (c >> 1)];
                    __half2 hv = *reinterpret_cast<__half2*>(&u);
                    float2 f = __half22float2(hv);
#pragma unroll
                    for (int j = 0; j < 2; j++) {
                        float v  = acc[mt][nt][h * 2 + j] + (j ? f.y : f.x);
                        float sv = silu_fast(v);
                        acc[mt][nt][h * 2 + j] = sv;
                        s += sv; q += sv * sv;
                    }
                }
                s += __shfl_xor_sync(0xffffffffu, s, 1);
                s += __shfl_xor_sync(0xffffffffu, s, 2);
                q += __shfl_xor_sync(0xffffffffu, q, 1);
                q += __shfl_xor_sync(0xffffffffu, q, 2);
                if (t4 == 0) {
                    s_sum[wcol * 64 + row] = s;
                    s_sq[wcol * 64 + row]  = q;
                }
            }
        }
        barg(gid);

        // ---- LN + residual(from fp16 XB in smem) + out + scatter ----
#pragma unroll
        for (int mt = 0; mt < 2; mt++) {
#pragma unroll
            for (int h = 0; h < 2; h++) {
                const int row = wr * 32 + mt * 16 + h * 8 + g;
                const float tsum = s_sum[row] + s_sum[64 + row];
                const float tsq  = s_sq[row]  + s_sq[64 + row];
                const float mean = tsum * (1.f / 128.f);
                const float inv  = rsqrtf(tsq * (1.f / 128.f) - mean * mean + 1e-5f);
                const int    t   = tgt_idx[m0 + row];
                const size_t gm  = (size_t)(m0 + row);
                float* __restrict__ srow = g_sums + (size_t)t * D;
                float* __restrict__ orow = out + gm * D;
#pragma unroll
                for (int nt = 0; nt < 8; nt++) {
                    const int c = wcol * 64 + nt * 8 + t4 * 2;
                    float a0 = (acc[mt][nt][h * 2 + 0] - mean) * inv * s_g[c + 0] + s_b[c + 0];
                    float a1 = (acc[mt][nt][h * 2 + 1] - mean) * inv * s_g[c + 1] + s_b[c + 1];
                    float p0 = __shfl_xor_sync(0xffffffffu, a0, 1);
                    float p1 = __shfl_xor_sync(0xffffffffu, a1, 1);
                    if ((t4 & 1) == 0) {
                        uint2 ue = *(const uint2*)(smu + xb_off + row * SROW + (c >> 1));
                        float2 e0 = __half22float2(*reinterpret_cast<__half2*>(&ue.x));
                        float2 e1 = __half22float2(*reinterpret_cast<__half2*>(&ue.y));
                        *(float4*)(orow + c) = make_float4(e0.x + a0, e0.y + a1,
                                                           e1.x + p0, e1.y + p1);
                        red_v4(srow + c, a0, a1, p0, p1);
                    }
                }
                if (wcol == 0 && t4 == 0) atomicAdd(g_counts + t, 1.f);
            }
        }
        barg(gid);   // XB read in epilogue: protect before next staging
    }
}

// ======================= NODE kernel (two MMA passes) ======================
__global__ void __launch_bounds__(512, 1)
node_kernel(const float* __restrict__ tgt_feat,
            const float* __restrict__ W1,       // We2t
            const float* __restrict__ W2,       // Wt2t
            const float* __restrict__ gamma,
            const float* __restrict__ beta,
            float*       __restrict__ out)
{
    extern __shared__ uint32_t smu[];
    const uint32_t smb = smem_addr_u32(smu);

    const int tid  = threadIdx.x;
    const int gid  = tid >> 7;
    const int lt   = tid & 127;
    const int wid  = lt >> 5;
    const int lane = tid & 31;
    const int g    = lane >> 2;
    const int t4   = lane & 3;
    const int wr   = wid & 1;
    const int wcol = wid >> 1;

    float* s_sum = (float*)(smu + UOFF_SUM + gid * 128);
    float* s_sq  = (float*)(smu + UOFF_SQ  + gid * 128);
    float* s_g   = (float*)(smu + UOFF_G);
    float* s_b   = (float*)(smu + UOFF_B);
    const uint32_t xa_off = UOFF_X + gid * 2 * XBLK;
    const uint32_t xb_off = xa_off + XBLK;

    const int a_r  = (lane & 7) + ((lane >> 3) & 1) * 8;
    const int a_cu = ((lane >> 4) & 1) * 4;
    const int bq_r  = (lane & 7) + ((lane >> 4) & 1) * 8;
    const int bq_cu = ((lane >> 3) & 1) * 4;

    if (tid < 128) { s_g[tid] = gamma[tid]; s_b[tid] = beta[tid]; }

    for (int i = tid; i < 128 * 32; i += 512) {
        int n = i >> 5, k4 = (i & 31) << 2;
        float4 a = *(const float4*)(W1 + n * D + k4);
        float4 b = *(const float4*)(W2 + n * D + k4);
        uint2 ua, ub;
        ua.x = ph2(a.x, a.y); ua.y = ph2(a.z, a.w);
        ub.x = ph2(b.x, b.y); ub.y = ph2(b.z, b.w);
        *(uint2*)(smu + UOFF_W1 + n * SROW + (k4 >> 1)) = ua;
        *(uint2*)(smu + UOFF_W2 + n * SROW + (k4 >> 1)) = ub;
    }
    __syncthreads();

    for (int tile = blockIdx.x * 4 + gid; tile < NTN64; tile += gridDim.x * 4) {
        const int m0 = tile * TILE64;

#pragma unroll
        for (int j = 0; j < 16; j++) {
            int i = lt + 128 * j;
            int row = i >> 5, k4 = (i & 31) << 2;
            size_t gm = (size_t)(m0 + row);
            float inv = __fdividef(1.f, fmaxf(g_counts[gm], 1.f));
            float4 a = *(const float4*)(g_sums + gm * D + k4);
            float4 e = *(const float4*)(tgt_feat + gm * D + k4);
            uint2 u0, u1;
            u0.x = ph2(a.x * inv, a.y * inv);
            u0.y = ph2(a.z * inv, a.w * inv);
            u1.x = ph2(e.x, e.y);
            u1.y = ph2(e.z, e.w);
            *(uint2*)(smu + xa_off + row * SROW + (k4 >> 1)) = u0;
            *(uint2*)(smu + xb_off + row * SROW + (k4 >> 1)) = u1;
        }
        barg(gid);

        float acc[2][8][4];
#pragma unroll
        for (int mt = 0; mt < 2; mt++)
#pragma unroll
            for (int nt = 0; nt < 8; nt++)
#pragma unroll
                for (int j = 0; j < 4; j++) acc[mt][nt][j] = 0.f;

#pragma unroll
        for (int ks = 0; ks < 8; ks++) {
            uint32_t a0[2], a1[2], a2[2], a3[2];
#pragma unroll
            for (int mt = 0; mt < 2; mt++) {
                uint32_t ad = smb + (xa_off + (wr * 32 + mt * 16 + a_r) * SROW
                                     + ks * 8 + a_cu) * 4;
                ldsm_x4(a0[mt], a1[mt], a2[mt], a3[mt], ad);
            }
#pragma unroll
            for (int nt = 0; nt < 8; nt += 2) {
                uint32_t b0, b1, b2, b3;
                uint32_t bd = smb + (UOFF_W1 + (wcol * 64 + nt * 8 + bq_r) * SROW
                                     + ks * 8 + bq_cu) * 4;
                ldsm_x4(b0, b1, b2, b3, bd);
                mma16(acc[0][nt],     a0[0], a1[0], a2[0], a3[0], b0, b1);
                mma16(acc[1][nt],     a0[1], a1[1], a2[1], a3[1], b0, b1);
                mma16(acc[0][nt + 1], a0[0], a1[0], a2[0], a3[0], b2, b3);
                mma16(acc[1][nt + 1], a0[1], a1[1], a2[1], a3[1], b2, b3);
            }
        }
#pragma unroll
        for (int ks = 0; ks < 8; ks++) {
            uint32_t a0[2], a1[2], a2[2], a3[2];
#pragma unroll
            for (int mt = 0; mt < 2; mt++) {
                uint32_t ad = smb + (xb_off + (wr * 32 + mt * 16 + a_r) * SROW
                                     + ks * 8 + a_cu) * 4;
                ldsm_x4(a0[mt], a1[mt], a2[mt], a3[mt], ad);
            }
#pragma unroll
            for (int nt = 0; nt < 8; nt += 2) {
                uint32_t b0, b1, b2, b3;
                uint32_t bd = smb + (UOFF_W2 + (wcol * 64 + nt * 8 + bq_r) * SROW
                                     + ks * 8 + bq_cu) * 4;
                ldsm_x4(b0, b1, b2, b3, bd);
                mma16(acc[0][nt],     a0[0], a1[0], a2[0], a3[0], b0, b1);
                mma16(acc[1][nt],     a0[1], a1[1], a2[1], a3[1], b0, b1);
                mma16(acc[0][nt + 1], a0[0], a1[0], a2[0], a3[0], b2, b3);
                mma16(acc[1][nt + 1], a0[1], a1[1], a2[1], a3[1], b2, b3);
            }
        }

#pragma unroll
        for (int mt = 0; mt < 2; mt++) {
#pragma unroll
            for (int h = 0; h < 2; h++) {
                float s = 0.f, q = 0.f;
#pragma unroll
                for (int nt = 0; nt < 8; nt++) {
#pragma unroll
                    for (int j = 0; j < 2; j++) {
                        float v  = acc[mt][nt][h * 2 + j];
                        float sv = silu_fast(v);
                        acc[mt][nt][h * 2 + j] = sv;
                        s += sv; q += sv * sv;
                    }
                }
                s += __shfl_xor_sync(0xffffffffu, s, 1);
                s += __shfl_xor_sync(0xffffffffu, s, 2);
                q += __shfl_xor_sync(0xffffffffu, q, 1);
                q += __shfl_xor_sync(0xffffffffu, q, 2);
                if (t4 == 0) {
                    int row = wr * 32 + mt * 16 + h * 8 + g;
                    s_sum[wcol * 64 + row] = s;
                    s_sq[wcol * 64 + row]  = q;
                }
            }
        }
        barg(gid);

#pragma unroll
        for (int mt = 0; mt < 2; mt++) {
#pragma unroll
            for (int h = 0; h < 2; h++) {
                const int row = wr * 32 + mt * 16 + h * 8 + g;
                const float tsum = s_sum[row] + s_sum[64 + row];
                const float tsq  = s_sq[row]  + s_sq[64 + row];
                const float mean = tsum * (1.f / 128.f);
                const float inv  = rsqrtf(tsq * (1.f / 128.f) - mean * mean + 1e-5f);
                const size_t gm  = (size_t)(m0 + row);
                const float* __restrict__ er = tgt_feat + gm * D;
                float* __restrict__ orow = out + gm * D;
#pragma unroll
                for (int nt = 0; nt < 8; nt++) {
                    const int c = wcol * 64 + nt * 8 + t4 * 2;
                    float a0 = (acc[mt][nt][h * 2 + 0] - mean) * inv * s_g[c + 0] + s_b[c + 0];
                    float a1 = (acc[mt][nt][h * 2 + 1] - mean) * inv * s_g[c + 1] + s_b[c + 1];
                    float p0 = __shfl_xor_sync(0xffffffffu, a0, 1);
                    float p1 = __shfl_xor_sync(0xffffffffu, a1, 1);
                    if ((t4 & 1) == 0) {
                        float4 rs = *(const float4*)(er + c);
                        *(float4*)(orow + c) = make_float4(rs.x + a0, rs.y + a1,
                                                           rs.z + p0, rs.w + p1);
                    }
                }
            }
        }
    }
}

// ======================= launch =======================
extern "C" void kernel_launch(void* const* d_in, const int* in_sizes, int n_in,
                              void* d_out, int out_size) {
    const float* src_feat  = (const float*)d_in[0];
    const float* tgt_feat  = (const float*)d_in[1];
    const float* edge_feat = (const float*)d_in[2];
    const float* Ws2e      = (const float*)d_in[3];
    const float* We2e      = (const float*)d_in[4];
    const float* We2t      = (const float*)d_in[5];
    const float* Wt2t      = (const float*)d_in[6];
    const float* gamma1    = (const float*)d_in[7];
    const float* beta1     = (const float*)d_in[8];
    const float* gamma2    = (const float*)d_in[9];
    const float* beta2     = (const float*)d_in[10];
    const int*   src_idx   = (const int*)d_in[11];
    const int*   tgt_idx   = (const int*)d_in[12];
    float*       out       = (float*)d_out;

    cudaFuncSetAttribute(pre_kernel,
                         cudaFuncAttributeMaxDynamicSharedMemorySize, SMEM_BYTES);
    cudaFuncSetAttribute(edge_kernel,
                         cudaFuncAttributeMaxDynamicSharedMemorySize, SMEM_BYTES);
    cudaFuncSetAttribute(node_kernel,
                         cudaFuncAttributeMaxDynamicSharedMemorySize, SMEM_BYTES);

    zero_scratch_kernel<<<2048, 256>>>();

    pre_kernel<<<148, 512, SMEM_BYTES>>>(src_feat, tgt_feat, Ws2e);

    edge_kernel<<<148, 512, SMEM_BYTES>>>(
        edge_feat, We2e, gamma1, beta1, src_idx, tgt_idx, out);

    node_kernel<<<148, 512, SMEM_BYTES>>>(
        tgt_feat, We2t, Wt2t, gamma2, beta2, out + (size_t)N_EDGE * D);
}